// round 12
// baseline (speedup 1.0000x reference)
#include <cuda_runtime.h>
#include <cuda_fp16.h>
#include <math.h>

// ---------------- problem constants ----------------
#define N_NODES 50000
#define E_EDGES 800000
#define ET (E_EDGES + N_NODES)
#define NGRAPH 64
#define NEG_SLOPE 0.2f
#define NBLK_SCAN 196            // ceil(50000/256)
#define ECH (E_EDGES / 4)        // 200000 int4 edge chunks
#define ECH_HALF (ECH / 2)

// ---------------- device scratch ----------------
__device__ __half g_hth [N_NODES * 256];
__device__ __half g_acth[N_NODES * 256];
__device__ float  g_esrc[N_NODES * 4];
__device__ float  g_edst[N_NODES * 4];
__device__ int    g_deg   [N_NODES];
__device__ int    g_rowptr[N_NODES + 1];
__device__ int    g_cursor[N_NODES];
__device__ int    g_srclist[ET];
__device__ int    g_bsum[256];
__device__ int    g_boff[256];
__device__ float  g_pool[NGRAPH * 64];
__device__ float  g_cnt [NGRAPH];
__device__ int    g_done = 0;

// ---------------- CSR build (by destination) ----------------
__global__ void deg_init_kernel() {
    int i = blockIdx.x * blockDim.x + threadIdx.x;
    if (i < N_NODES) g_deg[i] = 1;     // self loop pre-counted
}

__global__ void count_deg_edges_kernel(const int* __restrict__ ei, int i0, int i1) {
    int i = i0 + blockIdx.x * blockDim.x + threadIdx.x;
    if (i >= i1) return;
    int4 d4 = reinterpret_cast<const int4*>(ei + E_EDGES)[i];
    atomicAdd(&g_deg[d4.x], 1);
    atomicAdd(&g_deg[d4.y], 1);
    atomicAdd(&g_deg[d4.z], 1);
    atomicAdd(&g_deg[d4.w], 1);
}

__global__ void deg_blocksum_kernel() {
    __shared__ int sm[256];
    int idx = blockIdx.x * 256 + threadIdx.x;
    sm[threadIdx.x] = (idx < N_NODES) ? g_deg[idx] : 0;
    __syncthreads();
    for (int o = 128; o > 0; o >>= 1) {
        if (threadIdx.x < o) sm[threadIdx.x] += sm[threadIdx.x + o];
        __syncthreads();
    }
    if (threadIdx.x == 0) g_bsum[blockIdx.x] = sm[0];
}

__global__ void bsum_scan_kernel() {
    int t = threadIdx.x;
    int lane = t & 31, w = t >> 5;
    int v = (t < NBLK_SCAN) ? g_bsum[t] : 0;
    int sc = v;
#pragma unroll
    for (int o = 1; o < 32; o <<= 1) {
        int u = __shfl_up_sync(0xFFFFFFFFu, sc, o);
        if (lane >= o) sc += u;
    }
    __shared__ int ws[8];
    if (lane == 31) ws[w] = sc;
    __syncthreads();
    if (t < 8) {
        int x = ws[t];
#pragma unroll
        for (int o = 1; o < 8; o <<= 1) {
            int u = __shfl_up_sync(0xFFu, x, o);
            if (t >= o) x += u;
        }
        ws[t] = x;
    }
    __syncthreads();
    int incl = sc + (w > 0 ? ws[w - 1] : 0);
    g_boff[t] = incl - v;
    if (t == NBLK_SCAN - 1) g_rowptr[N_NODES] = incl;
}

__global__ void rowptr_fill_kernel() {
    int t = threadIdx.x;
    int idx = blockIdx.x * 256 + t;
    int lane = t & 31, w = t >> 5;
    int v = (idx < N_NODES) ? g_deg[idx] : 0;
    int sc = v;
#pragma unroll
    for (int o = 1; o < 32; o <<= 1) {
        int u = __shfl_up_sync(0xFFFFFFFFu, sc, o);
        if (lane >= o) sc += u;
    }
    __shared__ int ws[8];
    if (lane == 31) ws[w] = sc;
    __syncthreads();
    if (t < 8) {
        int x = ws[t];
#pragma unroll
        for (int o = 1; o < 8; o <<= 1) {
            int u = __shfl_up_sync(0xFFu, x, o);
            if (t >= o) x += u;
        }
        ws[t] = x;
    }
    __syncthreads();
    if (idx < N_NODES) {
        int excl = g_boff[blockIdx.x] + (w > 0 ? ws[w - 1] : 0) + sc - v;
        g_rowptr[idx] = excl;
        g_cursor[idx] = excl + 1;
        g_srclist[excl] = idx;            // self loop
    }
}

__global__ void fill_csr_kernel(const int* __restrict__ ei, int i0, int i1) {
    int i = i0 + blockIdx.x * blockDim.x + threadIdx.x;
    if (i >= i1) return;
    int4 s4 = reinterpret_cast<const int4*>(ei)[i];
    int4 d4 = reinterpret_cast<const int4*>(ei + E_EDGES)[i];
    g_srclist[atomicAdd(&g_cursor[d4.x], 1)] = s4.x;
    g_srclist[atomicAdd(&g_cursor[d4.y], 1)] = s4.y;
    g_srclist[atomicAdd(&g_cursor[d4.z], 1)] = s4.z;
    g_srclist[atomicAdd(&g_cursor[d4.w], 1)] = s4.w;
}

// ---------------- fp16 tensor-core GEMM + fused attention epilogue ----------------
__device__ __forceinline__ void mma_f16(float* c, const unsigned* a, const unsigned* b) {
    asm volatile(
        "mma.sync.aligned.m16n8k16.row.col.f32.f16.f16.f32 "
        "{%0,%1,%2,%3},{%4,%5,%6,%7},{%8,%9},{%0,%1,%2,%3};"
        : "+f"(c[0]), "+f"(c[1]), "+f"(c[2]), "+f"(c[3])
        : "r"(a[0]), "r"(a[1]), "r"(a[2]), "r"(a[3]), "r"(b[0]), "r"(b[1]));
}

__device__ __forceinline__ void ldsm_x4(unsigned& r0, unsigned& r1, unsigned& r2,
                                        unsigned& r3, unsigned addr) {
    asm volatile("ldmatrix.sync.aligned.m8n8.x4.shared.b16 {%0,%1,%2,%3}, [%4];"
                 : "=r"(r0), "=r"(r1), "=r"(r2), "=r"(r3) : "r"(addr));
}

#define GBM 128
#define GBK 32
#define A_STRH 40
#define B_STRH 40

template <int GBNP, bool A32>
__global__ __launch_bounds__(256, 2)
void hgemm_attn_kernel(const void* __restrict__ Araw, const float* __restrict__ B,
                       const float* __restrict__ asrc, const float* __restrict__ adst,
                       int M, int K, int Nd, int H) {
    constexpr int NT   = GBNP / 16;
    constexpr int NGRP = 256 / GBNP;
    constexpr int KPG  = GBK / NGRP;
    __shared__ __half As[2][GBM * A_STRH];
    __shared__ __half Bs[2][GBNP * B_STRH];

    const int tid  = threadIdx.x;
    const int warp = tid >> 5, lane = tid & 31;
    const int wm = warp >> 1, wn = warp & 1;
    const int row0 = blockIdx.y * GBM, col0 = blockIdx.x * GBNP;
    const int g = lane >> 2, tg = lane & 3;
    const int ar = tid >> 1, ahf = (tid & 1) * 16;
    const int bn = tid % GBNP, bkq = (tid / GBNP) * KPG;

    const unsigned As_sh = (unsigned)__cvta_generic_to_shared(&As[0][0]);
    const unsigned Bs_sh = (unsigned)__cvta_generic_to_shared(&Bs[0][0]);
    const int a_lsel = (lane & 15) * A_STRH + (lane >> 4) * 8;
    const int b_lsel = (((lane >> 4) & 1) * 8 + (lane & 7)) * B_STRH + ((lane >> 3) & 1) * 8;

    float acc[2][NT][4] = {};
    uint4 a_pre[2];
    float afp[A32 ? 16 : 1];
    __half b_pre[KPG];

    auto ldg = [&](int k0) {
        bool ok = (row0 + ar) < M;
        if (A32) {
            const float* ap = (const float*)Araw + (size_t)(row0 + ar) * K + k0 + ahf;
#pragma unroll
            for (int j = 0; j < 4; j++)
                *(float4*)&afp[4 * j] = ok ? *(const float4*)(ap + 4 * j)
                                           : make_float4(0.f, 0.f, 0.f, 0.f);
        } else {
            const __half* ap = (const __half*)Araw + (size_t)(row0 + ar) * K + k0 + ahf;
            a_pre[0] = ok ? *(const uint4*)ap       : make_uint4(0, 0, 0, 0);
            a_pre[1] = ok ? *(const uint4*)(ap + 8) : make_uint4(0, 0, 0, 0);
        }
#pragma unroll
        for (int i = 0; i < KPG; i++)
            b_pre[i] = __float2half(B[(size_t)(k0 + bkq + i) * Nd + col0 + bn]);
    };
    auto sts = [&](int s) {
        if (A32) {
            __half ha[16];
#pragma unroll
            for (int j = 0; j < 16; j++) ha[j] = __float2half(afp[j]);
            *(uint4*)&As[s][ar * A_STRH + ahf]     = ((uint4*)ha)[0];
            *(uint4*)&As[s][ar * A_STRH + ahf + 8] = ((uint4*)ha)[1];
        } else {
            *(uint4*)&As[s][ar * A_STRH + ahf]     = a_pre[0];
            *(uint4*)&As[s][ar * A_STRH + ahf + 8] = a_pre[1];
        }
#pragma unroll
        for (int j = 0; j < KPG / 8; j++)
            *(uint4*)&Bs[s][bn * B_STRH + bkq + 8 * j] = *(uint4*)&b_pre[8 * j];
    };
    auto compute = [&](int s) {
#pragma unroll
        for (int ks = 0; ks < 2; ks++) {
            unsigned afr[2][4];
#pragma unroll
            for (int mt = 0; mt < 2; mt++) {
                unsigned addr = As_sh +
                    (unsigned)((s * GBM * A_STRH) +
                               (wm * 32 + mt * 16) * A_STRH + ks * 16 + a_lsel) * 2u;
                ldsm_x4(afr[mt][0], afr[mt][1], afr[mt][2], afr[mt][3], addr);
            }
            unsigned bfr[NT][2];
#pragma unroll
            for (int p = 0; p < NT / 2; p++) {
                unsigned addr = Bs_sh +
                    (unsigned)((s * GBNP * B_STRH) +
                               (wn * (GBNP / 2) + p * 16) * B_STRH + ks * 16 + b_lsel) * 2u;
                ldsm_x4(bfr[2 * p][0], bfr[2 * p][1], bfr[2 * p + 1][0], bfr[2 * p + 1][1], addr);
            }
#pragma unroll
            for (int mt = 0; mt < 2; mt++)
#pragma unroll
                for (int nt = 0; nt < NT; nt++)
                    mma_f16(acc[mt][nt], afr[mt], bfr[nt]);
        }
    };

    ldg(0); sts(0); __syncthreads();
    int nk = K / GBK;
    for (int i = 0; i < nk; i++) {
        if (i + 1 < nk) ldg((i + 1) * GBK);
        compute(i & 1);
        if (i + 1 < nk) sts((i + 1) & 1);
        __syncthreads();
    }

    // ---- epilogue 1: fp16 feature store ----
#pragma unroll
    for (int mt = 0; mt < 2; mt++)
#pragma unroll
        for (int nt = 0; nt < NT; nt++) {
            int r = row0 + wm * 32 + mt * 16 + g;
            int c = col0 + wn * (GBNP / 2) + nt * 8 + 2 * tg;
            if (r < M)
                *(__half2*)&g_hth[(size_t)r * Nd + c] =
                    __floats2half2_rn(acc[mt][nt][0], acc[mt][nt][1]);
            if (r + 8 < M)
                *(__half2*)&g_hth[(size_t)(r + 8) * Nd + c] =
                    __floats2half2_rn(acc[mt][nt][2], acc[mt][nt][3]);
        }

    // ---- epilogue 2: attention coefficients ----
    float ps[2][2] = {}, pd[2][2] = {};
    const int head = (GBNP == 64) ? blockIdx.x : (blockIdx.x * 2 + wn);
    const int hb = head * 64;
#pragma unroll
    for (int nt = 0; nt < NT; nt++) {
        int cl = (GBNP == 64) ? (wn * 32 + nt * 8 + 2 * tg) : (nt * 8 + 2 * tg);
        float as0 = asrc[hb + cl], as1 = asrc[hb + cl + 1];
        float ad0 = adst[hb + cl], ad1 = adst[hb + cl + 1];
#pragma unroll
        for (int mt = 0; mt < 2; mt++) {
            ps[mt][0] += acc[mt][nt][0] * as0 + acc[mt][nt][1] * as1;
            ps[mt][1] += acc[mt][nt][2] * as0 + acc[mt][nt][3] * as1;
            pd[mt][0] += acc[mt][nt][0] * ad0 + acc[mt][nt][1] * ad1;
            pd[mt][1] += acc[mt][nt][2] * ad0 + acc[mt][nt][3] * ad1;
        }
    }
#pragma unroll
    for (int o = 1; o < 4; o <<= 1) {
#pragma unroll
        for (int mt = 0; mt < 2; mt++)
#pragma unroll
            for (int rr = 0; rr < 2; rr++) {
                ps[mt][rr] += __shfl_xor_sync(0xFFFFFFFFu, ps[mt][rr], o);
                pd[mt][rr] += __shfl_xor_sync(0xFFFFFFFFu, pd[mt][rr], o);
            }
    }
    if (GBNP == 128) {
        if (tg == 0) {
#pragma unroll
            for (int mt = 0; mt < 2; mt++)
#pragma unroll
                for (int rr = 0; rr < 2; rr++) {
                    int r = row0 + wm * 32 + mt * 16 + g + rr * 8;
                    if (r < M) {
                        g_esrc[(size_t)r * H + head] = ps[mt][rr];
                        g_edst[(size_t)r * H + head] = pd[mt][rr];
                    }
                }
        }
    } else {
        float* sm_src = (float*)&As[0][0];
        float* sm_dst = sm_src + 2 * GBM;
        __syncthreads();
        if (tg == 0) {
#pragma unroll
            for (int mt = 0; mt < 2; mt++)
#pragma unroll
                for (int rr = 0; rr < 2; rr++) {
                    int rl = wm * 32 + mt * 16 + g + rr * 8;
                    sm_src[wn * GBM + rl] = ps[mt][rr];
                    sm_dst[wn * GBM + rl] = pd[mt][rr];
                }
        }
        __syncthreads();
        if (tid < GBM) {
            int r = row0 + tid;
            if (r < M) {
                g_esrc[(size_t)r * H + head] = sm_src[tid] + sm_src[GBM + tid];
                g_edst[(size_t)r * H + head] = sm_dst[tid] + sm_dst[GBM + tid];
            }
        }
    }
}

// ---------------- fused gather softmax + aggregation (x2 unroll) ----------------
// POOL: fused global mean pool; last block also computes the final linear output.
template <int H, bool RELU, bool OUT16, bool POOL>
__global__ void gat_agg_kernel(const int* __restrict__ rowptr,
                               const int* __restrict__ srclist,
                               const float* __restrict__ esrc,
                               const float* __restrict__ edst,
                               const uint4* __restrict__ hv4,
                               const float* __restrict__ bias,
                               __half* __restrict__ outh,
                               const int* __restrict__ batch,
                               const float* __restrict__ lin_w,
                               const float* __restrict__ lin_b,
                               float* __restrict__ out) {
    constexpr int HC  = H * 64;
    constexpr int TPG = HC / 8;
    constexpr int NPB = 128 / TPG;
    int node = blockIdx.x * NPB + threadIdx.x / TPG;
    bool active = (node < N_NODES);
    int t = threadIdx.x % TPG;
    int head = (H == 1) ? 0 : (t >> 3);

    __shared__ float sp[POOL ? 4 * 64 : 1];
    __shared__ float scnt[POOL ? 4 : 1];
    __shared__ int   sg0[1];
    int gbase = 0, grel = 0;
    if (POOL) {
        if (threadIdx.x == 0) sg0[0] = batch[min(blockIdx.x * NPB, N_NODES - 1)];
        for (int i = threadIdx.x; i < 4 * 64; i += 128) sp[i] = 0.f;
        if (threadIdx.x < 4) scnt[threadIdx.x] = 0.f;
        __syncthreads();
        gbase = sg0[0];
        if (active) grel = min(batch[node] - gbase, 3);
    }

    float acc[8] = {};
    float denom = 0.f;

    if (active) {
        int beg = rowptr[node];
        int end = rowptr[node + 1];
        float ed = edst[node * H + head];
        int i = beg;
        for (; i + 2 <= end; i += 2) {
            int s0 = srclist[i];
            int s1 = srclist[i + 1];
            float es0 = esrc[s0 * H + head];
            float es1 = esrc[s1 * H + head];
            uint4 u0 = hv4[(size_t)s0 * TPG + t];
            uint4 u1 = hv4[(size_t)s1 * TPG + t];
            float e0 = es0 + ed; e0 = (e0 > 0.f) ? e0 : NEG_SLOPE * e0;
            float e1 = es1 + ed; e1 = (e1 > 0.f) ? e1 : NEG_SLOPE * e1;
            float x0 = __expf(e0);
            float x1 = __expf(e1);
            denom += x0;
            denom += x1;
            unsigned uu0[4] = {u0.x, u0.y, u0.z, u0.w};
            unsigned uu1[4] = {u1.x, u1.y, u1.z, u1.w};
#pragma unroll
            for (int k = 0; k < 4; k++) {
                float2 f0 = __half22float2(*reinterpret_cast<__half2*>(&uu0[k]));
                float2 f1 = __half22float2(*reinterpret_cast<__half2*>(&uu1[k]));
                acc[2 * k]     = fmaf(x0, f0.x, acc[2 * k]);
                acc[2 * k + 1] = fmaf(x0, f0.y, acc[2 * k + 1]);
                acc[2 * k]     = fmaf(x1, f1.x, acc[2 * k]);
                acc[2 * k + 1] = fmaf(x1, f1.y, acc[2 * k + 1]);
            }
        }
        if (i < end) {
            int s = srclist[i];
            float e = esrc[s * H + head] + ed;
            e = (e > 0.f) ? e : NEG_SLOPE * e;
            float ex = __expf(e);
            denom += ex;
            uint4 u = hv4[(size_t)s * TPG + t];
            unsigned uu[4] = {u.x, u.y, u.z, u.w};
#pragma unroll
            for (int k = 0; k < 4; k++) {
                float2 f = __half22float2(*reinterpret_cast<__half2*>(&uu[k]));
                acc[2 * k]     = fmaf(ex, f.x, acc[2 * k]);
                acc[2 * k + 1] = fmaf(ex, f.y, acc[2 * k + 1]);
            }
        }
    }

    float inv = active ? 1.f / (denom + 1e-16f) : 0.f;
    int c0 = t * 8;
    float o[8];
#pragma unroll
    for (int k = 0; k < 8; k++) {
        float v = acc[k] * inv + (active ? bias[c0 + k] : 0.f);
        o[k] = RELU ? fmaxf(v, 0.f) : v;
    }
    if (OUT16) {
        if (active) {
            __half hbuf[8];
#pragma unroll
            for (int k = 0; k < 8; k++) hbuf[k] = __float2half(o[k]);
            *(uint4*)&outh[(size_t)node * HC + c0] = *(uint4*)hbuf;
        }
    }
    if (POOL) {
        if (active) {
#pragma unroll
            for (int k = 0; k < 8; k++)
                atomicAdd(&sp[grel * 64 + c0 + k], o[k]);
            if (t == 0) atomicAdd(&scnt[grel], 1.f);
        }
        __syncthreads();
        for (int i = threadIdx.x; i < 4 * 64; i += 128) {
            float v = sp[i];
            if (v != 0.f) atomicAdd(&g_pool[(gbase + (i >> 6)) * 64 + (i & 63)], v);
        }
        if (threadIdx.x < 4 && scnt[threadIdx.x] != 0.f)
            atomicAdd(&g_cnt[gbase + threadIdx.x], scnt[threadIdx.x]);

        // ---- fused finalize: last block computes out[64] ----
        __threadfence();
        __shared__ int slast;
        if (threadIdx.x == 0) {
            int v = atomicAdd(&g_done, 1);
            slast = (v == (int)gridDim.x - 1);
        }
        __syncthreads();
        if (slast) {
            if (threadIdx.x == 0) g_done = 0;   // reset for next graph replay
            if (threadIdx.x < NGRAPH) {
                int gq = threadIdx.x;
                float cnt = fmaxf(g_cnt[gq], 1.f);
                float s = 0.f;
                for (int c = 0; c < 64; c++)
                    s += g_pool[gq * 64 + c] * lin_w[c];
                out[gq] = s / cnt + lin_b[0];
            }
        }
    }
}

// ---------------- launch ----------------
extern "C" void kernel_launch(void* const* d_in, const int* in_sizes, int n_in,
                              void* d_out, int out_size) {
    (void)in_sizes; (void)n_in; (void)out_size;
    const float* x      = (const float*)d_in[0];
    const int*   ei     = (const int*)  d_in[1];
    const int*   batch  = (const int*)  d_in[2];
    const float* W0     = (const float*)d_in[3];
    const float* asrc0  = (const float*)d_in[4];
    const float* adst0  = (const float*)d_in[5];
    const float* b0     = (const float*)d_in[6];
    const float* W1     = (const float*)d_in[7];
    const float* asrc1  = (const float*)d_in[8];
    const float* adst1  = (const float*)d_in[9];
    const float* b1     = (const float*)d_in[10];
    const float* W2     = (const float*)d_in[11];
    const float* asrc2  = (const float*)d_in[12];
    const float* adst2  = (const float*)d_in[13];
    const float* b2     = (const float*)d_in[14];
    const float* lin_w  = (const float*)d_in[15];
    const float* lin_b  = (const float*)d_in[16];
    float* out = (float*)d_out;

    static cudaStream_t s2 = nullptr;
    static cudaEvent_t ev_start, ev_init, ev_cntB, ev_row, ev_fillA;
    if (!s2) {
        cudaStreamCreateWithFlags(&s2, cudaStreamNonBlocking);
        cudaEventCreateWithFlags(&ev_start, cudaEventDisableTiming);
        cudaEventCreateWithFlags(&ev_init,  cudaEventDisableTiming);
        cudaEventCreateWithFlags(&ev_cntB,  cudaEventDisableTiming);
        cudaEventCreateWithFlags(&ev_row,   cudaEventDisableTiming);
        cudaEventCreateWithFlags(&ev_fillA, cudaEventDisableTiming);
    }

    void *p_acth_v, *p_pool_v, *p_cnt_v;
    void *p_row_v, *p_src_v, *p_es_v, *p_ed_v, *p_hth_v;
    cudaGetSymbolAddress(&p_acth_v, g_acth);
    cudaGetSymbolAddress(&p_pool_v, g_pool);
    cudaGetSymbolAddress(&p_cnt_v, g_cnt);
    cudaGetSymbolAddress(&p_row_v, g_rowptr);
    cudaGetSymbolAddress(&p_src_v, g_srclist);
    cudaGetSymbolAddress(&p_es_v, g_esrc);
    cudaGetSymbolAddress(&p_ed_v, g_edst);
    cudaGetSymbolAddress(&p_hth_v, g_hth);
    __half* p_acth = (__half*)p_acth_v;
    const int* p_row = (const int*)p_row_v;
    const int* p_src = (const int*)p_src_v;
    const float* p_es = (const float*)p_es_v;
    const float* p_ed = (const float*)p_ed_v;
    const uint4* p_hv = (const uint4*)p_hth_v;

    dim3 grid_big(2, (N_NODES + GBM - 1) / GBM);    // GBNP=128
    dim3 grid_sml(1, (N_NODES + GBM - 1) / GBM);    // GBNP=64

    // ---- fork ----
    cudaEventRecord(ev_start, 0);
    cudaStreamWaitEvent(s2, ev_start, 0);

    // side stream: memsets + deg init + first half of counting
    cudaMemsetAsync(p_pool_v, 0, NGRAPH * 64 * sizeof(float), s2);
    cudaMemsetAsync(p_cnt_v, 0, NGRAPH * sizeof(float), s2);
    deg_init_kernel<<<(N_NODES + 255) / 256, 256, 0, s2>>>();
    cudaEventRecord(ev_init, s2);
    count_deg_edges_kernel<<<(ECH_HALF + 255) / 256, 256, 0, s2>>>(ei, 0, ECH_HALF);

    // main stream: GEMM0 (fused fp32->fp16 A conversion), concurrent with CSR
    hgemm_attn_kernel<128, true><<<grid_big, 256>>>(x, W0, asrc0, adst0, N_NODES, 128, 256, 4);
    // main helps with second half of counting
    cudaStreamWaitEvent(0, ev_init, 0);
    count_deg_edges_kernel<<<(ECH - ECH_HALF + 255) / 256, 256>>>(ei, ECH_HALF, ECH);
    cudaEventRecord(ev_cntB, 0);

    // side stream: scans (needs all counts)
    cudaStreamWaitEvent(s2, ev_cntB, 0);
    deg_blocksum_kernel<<<NBLK_SCAN, 256, 0, s2>>>();
    bsum_scan_kernel<<<1, 256, 0, s2>>>();
    rowptr_fill_kernel<<<NBLK_SCAN, 256, 0, s2>>>();
    cudaEventRecord(ev_row, s2);
    fill_csr_kernel<<<(ECH_HALF + 255) / 256, 256, 0, s2>>>(ei, 0, ECH_HALF);
    cudaEventRecord(ev_fillA, s2);

    // main: second half of fill, then join
    cudaStreamWaitEvent(0, ev_row, 0);
    fill_csr_kernel<<<(ECH - ECH_HALF + 255) / 256, 256>>>(ei, ECH_HALF, ECH);
    cudaStreamWaitEvent(0, ev_fillA, 0);

    // ---- layers (sequential on main) ----
    gat_agg_kernel<4, true, true, false><<<(N_NODES + 3) / 4, 128>>>(
        p_row, p_src, p_es, p_ed, p_hv, b0, p_acth, nullptr, nullptr, nullptr, nullptr);

    hgemm_attn_kernel<128, false><<<grid_big, 256>>>(p_acth, W1, asrc1, adst1, N_NODES, 256, 256, 4);
    gat_agg_kernel<4, true, true, false><<<(N_NODES + 3) / 4, 128>>>(
        p_row, p_src, p_es, p_ed, p_hv, b1, p_acth, nullptr, nullptr, nullptr, nullptr);

    hgemm_attn_kernel<64, false><<<grid_sml, 256>>>(p_acth, W2, asrc2, adst2, N_NODES, 256, 64, 1);
    gat_agg_kernel<1, false, false, true><<<(N_NODES + 15) / 16, 128>>>(
        p_row, p_src, p_es, p_ed, p_hv, b2, nullptr, batch, lin_w, lin_b, out);
}

// round 13
// speedup vs baseline: 1.0203x; 1.0203x over previous
#include <cuda_runtime.h>
#include <cuda_fp16.h>
#include <math.h>

// ---------------- problem constants ----------------
#define N_NODES 50000
#define E_EDGES 800000
#define ET (E_EDGES + N_NODES)
#define NGRAPH 64
#define NEG_SLOPE 0.2f
#define NBLK_SCAN 196            // ceil(50000/256)
#define ECH (E_EDGES / 4)        // 200000 int4 edge chunks

// ---------------- device scratch ----------------
__device__ __half g_hth [N_NODES * 256];
__device__ __half g_acth[N_NODES * 256];
__device__ float  g_esrc[N_NODES * 4];
__device__ float  g_edst[N_NODES * 4];
__device__ int    g_deg   [N_NODES];
__device__ int    g_rowptr[N_NODES + 1];
__device__ int    g_cursor[N_NODES];
__device__ int    g_srclist[ET];
__device__ int    g_bsum[256];
__device__ int    g_boff[256];
__device__ float  g_pool[NGRAPH * 64];
__device__ float  g_cnt [NGRAPH];
__device__ int    g_done = 0;

// ---------------- CSR build (by destination) ----------------
__global__ void deg_init_kernel() {
    int i = blockIdx.x * blockDim.x + threadIdx.x;
    if (i < N_NODES) g_deg[i] = 1;     // self loop pre-counted
}

__global__ void count_deg_edges_kernel(const int* __restrict__ ei) {
    int i = blockIdx.x * blockDim.x + threadIdx.x;
    if (i >= ECH) return;
    int4 d4 = reinterpret_cast<const int4*>(ei + E_EDGES)[i];
    atomicAdd(&g_deg[d4.x], 1);
    atomicAdd(&g_deg[d4.y], 1);
    atomicAdd(&g_deg[d4.z], 1);
    atomicAdd(&g_deg[d4.w], 1);
}

__global__ void deg_blocksum_kernel() {
    __shared__ int sm[256];
    int idx = blockIdx.x * 256 + threadIdx.x;
    sm[threadIdx.x] = (idx < N_NODES) ? g_deg[idx] : 0;
    __syncthreads();
    for (int o = 128; o > 0; o >>= 1) {
        if (threadIdx.x < o) sm[threadIdx.x] += sm[threadIdx.x + o];
        __syncthreads();
    }
    if (threadIdx.x == 0) g_bsum[blockIdx.x] = sm[0];
}

__global__ void bsum_scan_kernel() {
    int t = threadIdx.x;
    int lane = t & 31, w = t >> 5;
    int v = (t < NBLK_SCAN) ? g_bsum[t] : 0;
    int sc = v;
#pragma unroll
    for (int o = 1; o < 32; o <<= 1) {
        int u = __shfl_up_sync(0xFFFFFFFFu, sc, o);
        if (lane >= o) sc += u;
    }
    __shared__ int ws[8];
    if (lane == 31) ws[w] = sc;
    __syncthreads();
    if (t < 8) {
        int x = ws[t];
#pragma unroll
        for (int o = 1; o < 8; o <<= 1) {
            int u = __shfl_up_sync(0xFFu, x, o);
            if (t >= o) x += u;
        }
        ws[t] = x;
    }
    __syncthreads();
    int incl = sc + (w > 0 ? ws[w - 1] : 0);
    g_boff[t] = incl - v;
    if (t == NBLK_SCAN - 1) g_rowptr[N_NODES] = incl;
}

__global__ void rowptr_fill_kernel() {
    int t = threadIdx.x;
    int idx = blockIdx.x * 256 + t;
    int lane = t & 31, w = t >> 5;
    int v = (idx < N_NODES) ? g_deg[idx] : 0;
    int sc = v;
#pragma unroll
    for (int o = 1; o < 32; o <<= 1) {
        int u = __shfl_up_sync(0xFFFFFFFFu, sc, o);
        if (lane >= o) sc += u;
    }
    __shared__ int ws[8];
    if (lane == 31) ws[w] = sc;
    __syncthreads();
    if (t < 8) {
        int x = ws[t];
#pragma unroll
        for (int o = 1; o < 8; o <<= 1) {
            int u = __shfl_up_sync(0xFFu, x, o);
            if (t >= o) x += u;
        }
        ws[t] = x;
    }
    __syncthreads();
    if (idx < N_NODES) {
        int excl = g_boff[blockIdx.x] + (w > 0 ? ws[w - 1] : 0) + sc - v;
        g_rowptr[idx] = excl;
        g_cursor[idx] = excl + 1;
        g_srclist[excl] = idx;            // self loop
    }
}

__global__ void fill_csr_kernel(const int* __restrict__ ei) {
    int i = blockIdx.x * blockDim.x + threadIdx.x;
    if (i >= ECH) return;
    int4 s4 = reinterpret_cast<const int4*>(ei)[i];
    int4 d4 = reinterpret_cast<const int4*>(ei + E_EDGES)[i];
    g_srclist[atomicAdd(&g_cursor[d4.x], 1)] = s4.x;
    g_srclist[atomicAdd(&g_cursor[d4.y], 1)] = s4.y;
    g_srclist[atomicAdd(&g_cursor[d4.z], 1)] = s4.z;
    g_srclist[atomicAdd(&g_cursor[d4.w], 1)] = s4.w;
}

// ---------------- fp16 tensor-core GEMM + fused attention epilogue ----------------
__device__ __forceinline__ void mma_f16(float* c, const unsigned* a, const unsigned* b) {
    asm volatile(
        "mma.sync.aligned.m16n8k16.row.col.f32.f16.f16.f32 "
        "{%0,%1,%2,%3},{%4,%5,%6,%7},{%8,%9},{%0,%1,%2,%3};"
        : "+f"(c[0]), "+f"(c[1]), "+f"(c[2]), "+f"(c[3])
        : "r"(a[0]), "r"(a[1]), "r"(a[2]), "r"(a[3]), "r"(b[0]), "r"(b[1]));
}

__device__ __forceinline__ void ldsm_x4(unsigned& r0, unsigned& r1, unsigned& r2,
                                        unsigned& r3, unsigned addr) {
    asm volatile("ldmatrix.sync.aligned.m8n8.x4.shared.b16 {%0,%1,%2,%3}, [%4];"
                 : "=r"(r0), "=r"(r1), "=r"(r2), "=r"(r3) : "r"(addr));
}

#define GBM 128
#define GBK 32
#define A_STRH 40
#define B_STRH 40

template <int GBNP, bool A32>
__global__ __launch_bounds__(256, 2)
void hgemm_attn_kernel(const void* __restrict__ Araw, const float* __restrict__ B,
                       const float* __restrict__ asrc, const float* __restrict__ adst,
                       int M, int K, int Nd, int H) {
    constexpr int NT   = GBNP / 16;
    constexpr int NGRP = 256 / GBNP;
    constexpr int KPG  = GBK / NGRP;
    __shared__ __half As[2][GBM * A_STRH];
    __shared__ __half Bs[2][GBNP * B_STRH];

    const int tid  = threadIdx.x;
    const int warp = tid >> 5, lane = tid & 31;
    const int wm = warp >> 1, wn = warp & 1;
    const int row0 = blockIdx.y * GBM, col0 = blockIdx.x * GBNP;
    const int g = lane >> 2, tg = lane & 3;
    const int ar = tid >> 1, ahf = (tid & 1) * 16;
    const int bn = tid % GBNP, bkq = (tid / GBNP) * KPG;

    const unsigned As_sh = (unsigned)__cvta_generic_to_shared(&As[0][0]);
    const unsigned Bs_sh = (unsigned)__cvta_generic_to_shared(&Bs[0][0]);
    const int a_lsel = (lane & 15) * A_STRH + (lane >> 4) * 8;
    const int b_lsel = (((lane >> 4) & 1) * 8 + (lane & 7)) * B_STRH + ((lane >> 3) & 1) * 8;

    float acc[2][NT][4] = {};
    uint4 a_pre[2];
    float afp[A32 ? 16 : 1];
    __half b_pre[KPG];

    auto ldg = [&](int k0) {
        bool ok = (row0 + ar) < M;
        if (A32) {
            const float* ap = (const float*)Araw + (size_t)(row0 + ar) * K + k0 + ahf;
#pragma unroll
            for (int j = 0; j < 4; j++)
                *(float4*)&afp[4 * j] = ok ? *(const float4*)(ap + 4 * j)
                                           : make_float4(0.f, 0.f, 0.f, 0.f);
        } else {
            const __half* ap = (const __half*)Araw + (size_t)(row0 + ar) * K + k0 + ahf;
            a_pre[0] = ok ? *(const uint4*)ap       : make_uint4(0, 0, 0, 0);
            a_pre[1] = ok ? *(const uint4*)(ap + 8) : make_uint4(0, 0, 0, 0);
        }
#pragma unroll
        for (int i = 0; i < KPG; i++)
            b_pre[i] = __float2half(B[(size_t)(k0 + bkq + i) * Nd + col0 + bn]);
    };
    auto sts = [&](int s) {
        if (A32) {
            __half ha[16];
#pragma unroll
            for (int j = 0; j < 16; j++) ha[j] = __float2half(afp[j]);
            *(uint4*)&As[s][ar * A_STRH + ahf]     = ((uint4*)ha)[0];
            *(uint4*)&As[s][ar * A_STRH + ahf + 8] = ((uint4*)ha)[1];
        } else {
            *(uint4*)&As[s][ar * A_STRH + ahf]     = a_pre[0];
            *(uint4*)&As[s][ar * A_STRH + ahf + 8] = a_pre[1];
        }
#pragma unroll
        for (int j = 0; j < KPG / 8; j++)
            *(uint4*)&Bs[s][bn * B_STRH + bkq + 8 * j] = *(uint4*)&b_pre[8 * j];
    };
    auto compute = [&](int s) {
#pragma unroll
        for (int ks = 0; ks < 2; ks++) {
            unsigned afr[2][4];
#pragma unroll
            for (int mt = 0; mt < 2; mt++) {
                unsigned addr = As_sh +
                    (unsigned)((s * GBM * A_STRH) +
                               (wm * 32 + mt * 16) * A_STRH + ks * 16 + a_lsel) * 2u;
                ldsm_x4(afr[mt][0], afr[mt][1], afr[mt][2], afr[mt][3], addr);
            }
            unsigned bfr[NT][2];
#pragma unroll
            for (int p = 0; p < NT / 2; p++) {
                unsigned addr = Bs_sh +
                    (unsigned)((s * GBNP * B_STRH) +
                               (wn * (GBNP / 2) + p * 16) * B_STRH + ks * 16 + b_lsel) * 2u;
                ldsm_x4(bfr[2 * p][0], bfr[2 * p][1], bfr[2 * p + 1][0], bfr[2 * p + 1][1], addr);
            }
#pragma unroll
            for (int mt = 0; mt < 2; mt++)
#pragma unroll
                for (int nt = 0; nt < NT; nt++)
                    mma_f16(acc[mt][nt], afr[mt], bfr[nt]);
        }
    };

    ldg(0); sts(0); __syncthreads();
    int nk = K / GBK;
    for (int i = 0; i < nk; i++) {
        if (i + 1 < nk) ldg((i + 1) * GBK);
        compute(i & 1);
        if (i + 1 < nk) sts((i + 1) & 1);
        __syncthreads();
    }

    // ---- epilogue 1: fp16 feature store ----
#pragma unroll
    for (int mt = 0; mt < 2; mt++)
#pragma unroll
        for (int nt = 0; nt < NT; nt++) {
            int r = row0 + wm * 32 + mt * 16 + g;
            int c = col0 + wn * (GBNP / 2) + nt * 8 + 2 * tg;
            if (r < M)
                *(__half2*)&g_hth[(size_t)r * Nd + c] =
                    __floats2half2_rn(acc[mt][nt][0], acc[mt][nt][1]);
            if (r + 8 < M)
                *(__half2*)&g_hth[(size_t)(r + 8) * Nd + c] =
                    __floats2half2_rn(acc[mt][nt][2], acc[mt][nt][3]);
        }

    // ---- epilogue 2: attention coefficients ----
    float ps[2][2] = {}, pd[2][2] = {};
    const int head = (GBNP == 64) ? blockIdx.x : (blockIdx.x * 2 + wn);
    const int hb = head * 64;
#pragma unroll
    for (int nt = 0; nt < NT; nt++) {
        int cl = (GBNP == 64) ? (wn * 32 + nt * 8 + 2 * tg) : (nt * 8 + 2 * tg);
        float as0 = asrc[hb + cl], as1 = asrc[hb + cl + 1];
        float ad0 = adst[hb + cl], ad1 = adst[hb + cl + 1];
#pragma unroll
        for (int mt = 0; mt < 2; mt++) {
            ps[mt][0] += acc[mt][nt][0] * as0 + acc[mt][nt][1] * as1;
            ps[mt][1] += acc[mt][nt][2] * as0 + acc[mt][nt][3] * as1;
            pd[mt][0] += acc[mt][nt][0] * ad0 + acc[mt][nt][1] * ad1;
            pd[mt][1] += acc[mt][nt][2] * ad0 + acc[mt][nt][3] * ad1;
        }
    }
#pragma unroll
    for (int o = 1; o < 4; o <<= 1) {
#pragma unroll
        for (int mt = 0; mt < 2; mt++)
#pragma unroll
            for (int rr = 0; rr < 2; rr++) {
                ps[mt][rr] += __shfl_xor_sync(0xFFFFFFFFu, ps[mt][rr], o);
                pd[mt][rr] += __shfl_xor_sync(0xFFFFFFFFu, pd[mt][rr], o);
            }
    }
    if (GBNP == 128) {
        if (tg == 0) {
#pragma unroll
            for (int mt = 0; mt < 2; mt++)
#pragma unroll
                for (int rr = 0; rr < 2; rr++) {
                    int r = row0 + wm * 32 + mt * 16 + g + rr * 8;
                    if (r < M) {
                        g_esrc[(size_t)r * H + head] = ps[mt][rr];
                        g_edst[(size_t)r * H + head] = pd[mt][rr];
                    }
                }
        }
    } else {
        float* sm_src = (float*)&As[0][0];
        float* sm_dst = sm_src + 2 * GBM;
        __syncthreads();
        if (tg == 0) {
#pragma unroll
            for (int mt = 0; mt < 2; mt++)
#pragma unroll
                for (int rr = 0; rr < 2; rr++) {
                    int rl = wm * 32 + mt * 16 + g + rr * 8;
                    sm_src[wn * GBM + rl] = ps[mt][rr];
                    sm_dst[wn * GBM + rl] = pd[mt][rr];
                }
        }
        __syncthreads();
        if (tid < GBM) {
            int r = row0 + tid;
            if (r < M) {
                g_esrc[(size_t)r * H + head] = sm_src[tid] + sm_src[GBM + tid];
                g_edst[(size_t)r * H + head] = sm_dst[tid] + sm_dst[GBM + tid];
            }
        }
    }
}

// ---------------- fused gather softmax + aggregation (x2 unroll) ----------------
// POOL: fused global mean pool; last block also computes the final linear output.
template <int H, bool RELU, bool OUT16, bool POOL>
__global__ void gat_agg_kernel(const int* __restrict__ rowptr,
                               const int* __restrict__ srclist,
                               const float* __restrict__ esrc,
                               const float* __restrict__ edst,
                               const uint4* __restrict__ hv4,
                               const float* __restrict__ bias,
                               __half* __restrict__ outh,
                               const int* __restrict__ batch,
                               const float* __restrict__ lin_w,
                               const float* __restrict__ lin_b,
                               float* __restrict__ out) {
    constexpr int HC  = H * 64;
    constexpr int TPG = HC / 8;
    constexpr int NPB = 128 / TPG;
    int node = blockIdx.x * NPB + threadIdx.x / TPG;
    bool active = (node < N_NODES);
    int t = threadIdx.x % TPG;
    int head = (H == 1) ? 0 : (t >> 3);

    __shared__ float sp[POOL ? 4 * 64 : 1];
    __shared__ float scnt[POOL ? 4 : 1];
    __shared__ int   sg0[1];
    int gbase = 0, grel = 0;
    if (POOL) {
        if (threadIdx.x == 0) sg0[0] = batch[min(blockIdx.x * NPB, N_NODES - 1)];
        for (int i = threadIdx.x; i < 4 * 64; i += 128) sp[i] = 0.f;
        if (threadIdx.x < 4) scnt[threadIdx.x] = 0.f;
        __syncthreads();
        gbase = sg0[0];
        if (active) grel = min(batch[node] - gbase, 3);
    }

    float acc[8] = {};
    float denom = 0.f;

    if (active) {
        int beg = rowptr[node];
        int end = rowptr[node + 1];
        float ed = edst[node * H + head];
        int i = beg;
        for (; i + 2 <= end; i += 2) {
            int s0 = srclist[i];
            int s1 = srclist[i + 1];
            float es0 = esrc[s0 * H + head];
            float es1 = esrc[s1 * H + head];
            uint4 u0 = hv4[(size_t)s0 * TPG + t];
            uint4 u1 = hv4[(size_t)s1 * TPG + t];
            float e0 = es0 + ed; e0 = (e0 > 0.f) ? e0 : NEG_SLOPE * e0;
            float e1 = es1 + ed; e1 = (e1 > 0.f) ? e1 : NEG_SLOPE * e1;
            float x0 = __expf(e0);
            float x1 = __expf(e1);
            denom += x0;
            denom += x1;
            unsigned uu0[4] = {u0.x, u0.y, u0.z, u0.w};
            unsigned uu1[4] = {u1.x, u1.y, u1.z, u1.w};
#pragma unroll
            for (int k = 0; k < 4; k++) {
                float2 f0 = __half22float2(*reinterpret_cast<__half2*>(&uu0[k]));
                float2 f1 = __half22float2(*reinterpret_cast<__half2*>(&uu1[k]));
                acc[2 * k]     = fmaf(x0, f0.x, acc[2 * k]);
                acc[2 * k + 1] = fmaf(x0, f0.y, acc[2 * k + 1]);
                acc[2 * k]     = fmaf(x1, f1.x, acc[2 * k]);
                acc[2 * k + 1] = fmaf(x1, f1.y, acc[2 * k + 1]);
            }
        }
        if (i < end) {
            int s = srclist[i];
            float e = esrc[s * H + head] + ed;
            e = (e > 0.f) ? e : NEG_SLOPE * e;
            float ex = __expf(e);
            denom += ex;
            uint4 u = hv4[(size_t)s * TPG + t];
            unsigned uu[4] = {u.x, u.y, u.z, u.w};
#pragma unroll
            for (int k = 0; k < 4; k++) {
                float2 f = __half22float2(*reinterpret_cast<__half2*>(&uu[k]));
                acc[2 * k]     = fmaf(ex, f.x, acc[2 * k]);
                acc[2 * k + 1] = fmaf(ex, f.y, acc[2 * k + 1]);
            }
        }
    }

    float inv = active ? 1.f / (denom + 1e-16f) : 0.f;
    int c0 = t * 8;
    float o[8];
#pragma unroll
    for (int k = 0; k < 8; k++) {
        float v = acc[k] * inv + (active ? bias[c0 + k] : 0.f);
        o[k] = RELU ? fmaxf(v, 0.f) : v;
    }
    if (OUT16) {
        if (active) {
            __half hbuf[8];
#pragma unroll
            for (int k = 0; k < 8; k++) hbuf[k] = __float2half(o[k]);
            *(uint4*)&outh[(size_t)node * HC + c0] = *(uint4*)hbuf;
        }
    }
    if (POOL) {
        if (active) {
#pragma unroll
            for (int k = 0; k < 8; k++)
                atomicAdd(&sp[grel * 64 + c0 + k], o[k]);
            if (t == 0) atomicAdd(&scnt[grel], 1.f);
        }
        __syncthreads();
        for (int i = threadIdx.x; i < 4 * 64; i += 128) {
            float v = sp[i];
            if (v != 0.f) atomicAdd(&g_pool[(gbase + (i >> 6)) * 64 + (i & 63)], v);
        }
        if (threadIdx.x < 4 && scnt[threadIdx.x] != 0.f)
            atomicAdd(&g_cnt[gbase + threadIdx.x], scnt[threadIdx.x]);

        // ---- fused finalize: last block computes out[64] ----
        __threadfence();
        __shared__ int slast;
        if (threadIdx.x == 0) {
            int v = atomicAdd(&g_done, 1);
            slast = (v == (int)gridDim.x - 1);
        }
        __syncthreads();
        if (slast) {
            if (threadIdx.x == 0) g_done = 0;   // reset for graph replay determinism
            if (threadIdx.x < NGRAPH) {
                int gq = threadIdx.x;
                float cnt = fmaxf(g_cnt[gq], 1.f);
                float s = 0.f;
                for (int c = 0; c < 64; c++)
                    s += g_pool[gq * 64 + c] * lin_w[c];
                out[gq] = s / cnt + lin_b[0];
            }
        }
    }
}

// ---------------- launch ----------------
extern "C" void kernel_launch(void* const* d_in, const int* in_sizes, int n_in,
                              void* d_out, int out_size) {
    (void)in_sizes; (void)n_in; (void)out_size;
    const float* x      = (const float*)d_in[0];
    const int*   ei     = (const int*)  d_in[1];
    const int*   batch  = (const int*)  d_in[2];
    const float* W0     = (const float*)d_in[3];
    const float* asrc0  = (const float*)d_in[4];
    const float* adst0  = (const float*)d_in[5];
    const float* b0     = (const float*)d_in[6];
    const float* W1     = (const float*)d_in[7];
    const float* asrc1  = (const float*)d_in[8];
    const float* adst1  = (const float*)d_in[9];
    const float* b1     = (const float*)d_in[10];
    const float* W2     = (const float*)d_in[11];
    const float* asrc2  = (const float*)d_in[12];
    const float* adst2  = (const float*)d_in[13];
    const float* b2     = (const float*)d_in[14];
    const float* lin_w  = (const float*)d_in[15];
    const float* lin_b  = (const float*)d_in[16];
    float* out = (float*)d_out;

    static cudaStream_t s2 = nullptr;
    static cudaEvent_t ev1 = nullptr, ev2 = nullptr;
    if (!s2) {
        cudaStreamCreateWithFlags(&s2, cudaStreamNonBlocking);
        cudaEventCreateWithFlags(&ev1, cudaEventDisableTiming);
        cudaEventCreateWithFlags(&ev2, cudaEventDisableTiming);
    }

    void *p_acth_v, *p_pool_v, *p_cnt_v;
    void *p_row_v, *p_src_v, *p_es_v, *p_ed_v, *p_hth_v;
    cudaGetSymbolAddress(&p_acth_v, g_acth);
    cudaGetSymbolAddress(&p_pool_v, g_pool);
    cudaGetSymbolAddress(&p_cnt_v, g_cnt);
    cudaGetSymbolAddress(&p_row_v, g_rowptr);
    cudaGetSymbolAddress(&p_src_v, g_srclist);
    cudaGetSymbolAddress(&p_es_v, g_esrc);
    cudaGetSymbolAddress(&p_ed_v, g_edst);
    cudaGetSymbolAddress(&p_hth_v, g_hth);
    __half* p_acth = (__half*)p_acth_v;
    const int* p_row = (const int*)p_row_v;
    const int* p_src = (const int*)p_src_v;
    const float* p_es = (const float*)p_es_v;
    const float* p_ed = (const float*)p_ed_v;
    const uint4* p_hv = (const uint4*)p_hth_v;

    dim3 grid_big(2, (N_NODES + GBM - 1) / GBM);    // GBNP=128
    dim3 grid_sml(1, (N_NODES + GBM - 1) / GBM);    // GBNP=64

    // ---- single fork: entire CSR build + memsets on side stream ----
    cudaEventRecord(ev1, 0);
    cudaStreamWaitEvent(s2, ev1, 0);
    cudaMemsetAsync(p_pool_v, 0, NGRAPH * 64 * sizeof(float), s2);
    cudaMemsetAsync(p_cnt_v, 0, NGRAPH * sizeof(float), s2);
    deg_init_kernel<<<(N_NODES + 255) / 256, 256, 0, s2>>>();
    count_deg_edges_kernel<<<(ECH + 255) / 256, 256, 0, s2>>>(ei);
    deg_blocksum_kernel<<<NBLK_SCAN, 256, 0, s2>>>();
    bsum_scan_kernel<<<1, 256, 0, s2>>>();
    rowptr_fill_kernel<<<NBLK_SCAN, 256, 0, s2>>>();
    fill_csr_kernel<<<(ECH + 255) / 256, 256, 0, s2>>>(ei);
    cudaEventRecord(ev2, s2);

    // ---- main stream: GEMM0 overlaps CSR build; single join before agg0 ----
    hgemm_attn_kernel<128, true><<<grid_big, 256>>>(x, W0, asrc0, adst0, N_NODES, 128, 256, 4);
    cudaStreamWaitEvent(0, ev2, 0);
    gat_agg_kernel<4, true, true, false><<<(N_NODES + 3) / 4, 128>>>(
        p_row, p_src, p_es, p_ed, p_hv, b0, p_acth, nullptr, nullptr, nullptr, nullptr);

    hgemm_attn_kernel<128, false><<<grid_big, 256>>>(p_acth, W1, asrc1, adst1, N_NODES, 256, 256, 4);
    gat_agg_kernel<4, true, true, false><<<(N_NODES + 3) / 4, 128>>>(
        p_row, p_src, p_es, p_ed, p_hv, b1, p_acth, nullptr, nullptr, nullptr, nullptr);

    hgemm_attn_kernel<64, false><<<grid_sml, 256>>>(p_acth, W2, asrc2, adst2, N_NODES, 256, 64, 1);
    gat_agg_kernel<1, false, false, true><<<(N_NODES + 15) / 16, 128>>>(
        p_row, p_src, p_es, p_ed, p_hv, b2, nullptr, batch, lin_w, lin_b, out);
}

// round 14
// speedup vs baseline: 1.0244x; 1.0041x over previous
#include <cuda_runtime.h>
#include <cuda_fp16.h>
#include <math.h>

// ---------------- problem constants ----------------
#define N_NODES 50000
#define E_EDGES 800000
#define ET (E_EDGES + N_NODES)
#define NGRAPH 64
#define NEG_SLOPE 0.2f
#define NBLK_SCAN 196            // ceil(50000/256)
#define ECH (E_EDGES / 4)        // 200000 int4 edge chunks

// ---------------- device scratch ----------------
__device__ __half g_hth [N_NODES * 256];
__device__ __half g_acth[N_NODES * 256];
__device__ float  g_esrc[N_NODES * 4];
__device__ float  g_edst[N_NODES * 4];
__device__ int    g_deg   [N_NODES];
__device__ int    g_rowptr[N_NODES + 1];
__device__ int    g_cursor[N_NODES];
__device__ int    g_srclist[ET];
__device__ int    g_bsum[256];
__device__ int    g_boff[256];
__device__ float  g_pool[NGRAPH * 64];
__device__ float  g_cnt [NGRAPH];
__device__ int    g_arrive = 0;
__device__ int    g_flag   = 0;
__device__ int    g_donect = 0;

// ---------------- CSR build (by destination) ----------------
__global__ void deg_init_kernel() {
    int i = blockIdx.x * blockDim.x + threadIdx.x;
    if (i < N_NODES) g_deg[i] = 1;     // self loop pre-counted
}

__global__ void count_deg_edges_kernel(const int* __restrict__ ei) {
    int i = blockIdx.x * blockDim.x + threadIdx.x;
    if (i >= ECH) return;
    int4 d4 = reinterpret_cast<const int4*>(ei + E_EDGES)[i];
    atomicAdd(&g_deg[d4.x], 1);
    atomicAdd(&g_deg[d4.y], 1);
    atomicAdd(&g_deg[d4.z], 1);
    atomicAdd(&g_deg[d4.w], 1);
}

// Fused 3-phase scan: blocksum -> cross-block scan -> rowptr fill.
// Grid-wide sync via spin barrier (196 blocks co-resident on 148 SMs).
__global__ void scan_rowptr_fused_kernel() {
    int t = threadIdx.x, b = blockIdx.x;
    int idx = b * 256 + t;
    int lane = t & 31, w = t >> 5;

    // --- phase 1: block-local inclusive scan + block sum ---
    int v = (idx < N_NODES) ? g_deg[idx] : 0;
    int sc = v;
#pragma unroll
    for (int o = 1; o < 32; o <<= 1) {
        int u = __shfl_up_sync(0xFFFFFFFFu, sc, o);
        if (lane >= o) sc += u;
    }
    __shared__ int ws[8];
    if (lane == 31) ws[w] = sc;
    __syncthreads();
    if (t < 8) {
        int x = ws[t];
#pragma unroll
        for (int o = 1; o < 8; o <<= 1) {
            int u = __shfl_up_sync(0xFFu, x, o);
            if (t >= o) x += u;
        }
        ws[t] = x;
    }
    __syncthreads();
    int blocksum = ws[7];
    if (t == 0) {
        g_bsum[b] = blocksum;
        __threadfence();
        atomicAdd(&g_arrive, 1);
    }

    // --- phase 2: block 0 scans the 196 block sums ---
    if (b == 0) {
        if (t == 0) {
            while (atomicAdd(&g_arrive, 0) < NBLK_SCAN) __nanosleep(64);
        }
        __syncthreads();
        int v2 = (t < NBLK_SCAN) ? g_bsum[t] : 0;
        int sc2 = v2;
#pragma unroll
        for (int o = 1; o < 32; o <<= 1) {
            int u = __shfl_up_sync(0xFFFFFFFFu, sc2, o);
            if (lane >= o) sc2 += u;
        }
        __shared__ int ws2[8];
        if (lane == 31) ws2[w] = sc2;
        __syncthreads();
        if (t < 8) {
            int x = ws2[t];
#pragma unroll
            for (int o = 1; o < 8; o <<= 1) {
                int u = __shfl_up_sync(0xFFu, x, o);
                if (t >= o) x += u;
            }
            ws2[t] = x;
        }
        __syncthreads();
        int incl = sc2 + (w > 0 ? ws2[w - 1] : 0);
        if (t < 256) g_boff[t] = incl - v2;
        if (t == NBLK_SCAN - 1) g_rowptr[N_NODES] = incl;
        __threadfence();
        __syncthreads();
        if (t == 0) atomicExch(&g_flag, 1);
    }

    // --- phase 3: all blocks wait, then fill rowptr/cursor/self-loop ---
    if (t == 0) {
        while (atomicAdd(&g_flag, 0) == 0) __nanosleep(64);
    }
    __syncthreads();
    if (idx < N_NODES) {
        int excl = g_boff[b] + (w > 0 ? ws[w - 1] : 0) + sc - v;
        g_rowptr[idx] = excl;
        g_cursor[idx] = excl + 1;         // slot 0 reserved for self loop
        g_srclist[excl] = idx;            // self loop filled here
    }
    // --- reset sync state for graph replay determinism ---
    __syncthreads();
    if (t == 0) {
        int d = atomicAdd(&g_donect, 1);
        if (d == NBLK_SCAN - 1) {
            g_arrive = 0;
            g_flag   = 0;
            g_donect = 0;
            __threadfence();
        }
    }
}

__global__ void fill_csr_kernel(const int* __restrict__ ei) {
    int i = blockIdx.x * blockDim.x + threadIdx.x;
    if (i >= ECH) return;
    int4 s4 = reinterpret_cast<const int4*>(ei)[i];
    int4 d4 = reinterpret_cast<const int4*>(ei + E_EDGES)[i];
    g_srclist[atomicAdd(&g_cursor[d4.x], 1)] = s4.x;
    g_srclist[atomicAdd(&g_cursor[d4.y], 1)] = s4.y;
    g_srclist[atomicAdd(&g_cursor[d4.z], 1)] = s4.z;
    g_srclist[atomicAdd(&g_cursor[d4.w], 1)] = s4.w;
}

// ---------------- fp16 tensor-core GEMM + fused attention epilogue ----------------
__device__ __forceinline__ void mma_f16(float* c, const unsigned* a, const unsigned* b) {
    asm volatile(
        "mma.sync.aligned.m16n8k16.row.col.f32.f16.f16.f32 "
        "{%0,%1,%2,%3},{%4,%5,%6,%7},{%8,%9},{%0,%1,%2,%3};"
        : "+f"(c[0]), "+f"(c[1]), "+f"(c[2]), "+f"(c[3])
        : "r"(a[0]), "r"(a[1]), "r"(a[2]), "r"(a[3]), "r"(b[0]), "r"(b[1]));
}

__device__ __forceinline__ void ldsm_x4(unsigned& r0, unsigned& r1, unsigned& r2,
                                        unsigned& r3, unsigned addr) {
    asm volatile("ldmatrix.sync.aligned.m8n8.x4.shared.b16 {%0,%1,%2,%3}, [%4];"
                 : "=r"(r0), "=r"(r1), "=r"(r2), "=r"(r3) : "r"(addr));
}

#define GBM 128
#define GBK 32
#define A_STRH 40
#define B_STRH 40

template <int GBNP, bool A32>
__global__ __launch_bounds__(256, 2)
void hgemm_attn_kernel(const void* __restrict__ Araw, const float* __restrict__ B,
                       const float* __restrict__ asrc, const float* __restrict__ adst,
                       int M, int K, int Nd, int H) {
    constexpr int NT   = GBNP / 16;
    constexpr int NGRP = 256 / GBNP;
    constexpr int KPG  = GBK / NGRP;
    __shared__ __half As[2][GBM * A_STRH];
    __shared__ __half Bs[2][GBNP * B_STRH];

    const int tid  = threadIdx.x;
    const int warp = tid >> 5, lane = tid & 31;
    const int wm = warp >> 1, wn = warp & 1;
    const int row0 = blockIdx.y * GBM, col0 = blockIdx.x * GBNP;
    const int g = lane >> 2, tg = lane & 3;
    const int ar = tid >> 1, ahf = (tid & 1) * 16;
    const int bn = tid % GBNP, bkq = (tid / GBNP) * KPG;

    const unsigned As_sh = (unsigned)__cvta_generic_to_shared(&As[0][0]);
    const unsigned Bs_sh = (unsigned)__cvta_generic_to_shared(&Bs[0][0]);
    const int a_lsel = (lane & 15) * A_STRH + (lane >> 4) * 8;
    const int b_lsel = (((lane >> 4) & 1) * 8 + (lane & 7)) * B_STRH + ((lane >> 3) & 1) * 8;

    float acc[2][NT][4] = {};
    uint4 a_pre[2];
    float afp[A32 ? 16 : 1];
    __half b_pre[KPG];

    auto ldg = [&](int k0) {
        bool ok = (row0 + ar) < M;
        if (A32) {
            const float* ap = (const float*)Araw + (size_t)(row0 + ar) * K + k0 + ahf;
#pragma unroll
            for (int j = 0; j < 4; j++)
                *(float4*)&afp[4 * j] = ok ? *(const float4*)(ap + 4 * j)
                                           : make_float4(0.f, 0.f, 0.f, 0.f);
        } else {
            const __half* ap = (const __half*)Araw + (size_t)(row0 + ar) * K + k0 + ahf;
            a_pre[0] = ok ? *(const uint4*)ap       : make_uint4(0, 0, 0, 0);
            a_pre[1] = ok ? *(const uint4*)(ap + 8) : make_uint4(0, 0, 0, 0);
        }
#pragma unroll
        for (int i = 0; i < KPG; i++)
            b_pre[i] = __float2half(B[(size_t)(k0 + bkq + i) * Nd + col0 + bn]);
    };
    auto sts = [&](int s) {
        if (A32) {
            __half ha[16];
#pragma unroll
            for (int j = 0; j < 16; j++) ha[j] = __float2half(afp[j]);
            *(uint4*)&As[s][ar * A_STRH + ahf]     = ((uint4*)ha)[0];
            *(uint4*)&As[s][ar * A_STRH + ahf + 8] = ((uint4*)ha)[1];
        } else {
            *(uint4*)&As[s][ar * A_STRH + ahf]     = a_pre[0];
            *(uint4*)&As[s][ar * A_STRH + ahf + 8] = a_pre[1];
        }
#pragma unroll
        for (int j = 0; j < KPG / 8; j++)
            *(uint4*)&Bs[s][bn * B_STRH + bkq + 8 * j] = *(uint4*)&b_pre[8 * j];
    };
    auto compute = [&](int s) {
#pragma unroll
        for (int ks = 0; ks < 2; ks++) {
            unsigned afr[2][4];
#pragma unroll
            for (int mt = 0; mt < 2; mt++) {
                unsigned addr = As_sh +
                    (unsigned)((s * GBM * A_STRH) +
                               (wm * 32 + mt * 16) * A_STRH + ks * 16 + a_lsel) * 2u;
                ldsm_x4(afr[mt][0], afr[mt][1], afr[mt][2], afr[mt][3], addr);
            }
            unsigned bfr[NT][2];
#pragma unroll
            for (int p = 0; p < NT / 2; p++) {
                unsigned addr = Bs_sh +
                    (unsigned)((s * GBNP * B_STRH) +
                               (wn * (GBNP / 2) + p * 16) * B_STRH + ks * 16 + b_lsel) * 2u;
                ldsm_x4(bfr[2 * p][0], bfr[2 * p][1], bfr[2 * p + 1][0], bfr[2 * p + 1][1], addr);
            }
#pragma unroll
            for (int mt = 0; mt < 2; mt++)
#pragma unroll
                for (int nt = 0; nt < NT; nt++)
                    mma_f16(acc[mt][nt], afr[mt], bfr[nt]);
        }
    };

    ldg(0); sts(0); __syncthreads();
    int nk = K / GBK;
    for (int i = 0; i < nk; i++) {
        if (i + 1 < nk) ldg((i + 1) * GBK);
        compute(i & 1);
        if (i + 1 < nk) sts((i + 1) & 1);
        __syncthreads();
    }

    // ---- epilogue 1: fp16 feature store ----
#pragma unroll
    for (int mt = 0; mt < 2; mt++)
#pragma unroll
        for (int nt = 0; nt < NT; nt++) {
            int r = row0 + wm * 32 + mt * 16 + g;
            int c = col0 + wn * (GBNP / 2) + nt * 8 + 2 * tg;
            if (r < M)
                *(__half2*)&g_hth[(size_t)r * Nd + c] =
                    __floats2half2_rn(acc[mt][nt][0], acc[mt][nt][1]);
            if (r + 8 < M)
                *(__half2*)&g_hth[(size_t)(r + 8) * Nd + c] =
                    __floats2half2_rn(acc[mt][nt][2], acc[mt][nt][3]);
        }

    // ---- epilogue 2: attention coefficients ----
    float ps[2][2] = {}, pd[2][2] = {};
    const int head = (GBNP == 64) ? blockIdx.x : (blockIdx.x * 2 + wn);
    const int hb = head * 64;
#pragma unroll
    for (int nt = 0; nt < NT; nt++) {
        int cl = (GBNP == 64) ? (wn * 32 + nt * 8 + 2 * tg) : (nt * 8 + 2 * tg);
        float as0 = asrc[hb + cl], as1 = asrc[hb + cl + 1];
        float ad0 = adst[hb + cl], ad1 = adst[hb + cl + 1];
#pragma unroll
        for (int mt = 0; mt < 2; mt++) {
            ps[mt][0] += acc[mt][nt][0] * as0 + acc[mt][nt][1] * as1;
            ps[mt][1] += acc[mt][nt][2] * as0 + acc[mt][nt][3] * as1;
            pd[mt][0] += acc[mt][nt][0] * ad0 + acc[mt][nt][1] * ad1;
            pd[mt][1] += acc[mt][nt][2] * ad0 + acc[mt][nt][3] * ad1;
        }
    }
#pragma unroll
    for (int o = 1; o < 4; o <<= 1) {
#pragma unroll
        for (int mt = 0; mt < 2; mt++)
#pragma unroll
            for (int rr = 0; rr < 2; rr++) {
                ps[mt][rr] += __shfl_xor_sync(0xFFFFFFFFu, ps[mt][rr], o);
                pd[mt][rr] += __shfl_xor_sync(0xFFFFFFFFu, pd[mt][rr], o);
            }
    }
    if (GBNP == 128) {
        if (tg == 0) {
#pragma unroll
            for (int mt = 0; mt < 2; mt++)
#pragma unroll
                for (int rr = 0; rr < 2; rr++) {
                    int r = row0 + wm * 32 + mt * 16 + g + rr * 8;
                    if (r < M) {
                        g_esrc[(size_t)r * H + head] = ps[mt][rr];
                        g_edst[(size_t)r * H + head] = pd[mt][rr];
                    }
                }
        }
    } else {
        float* sm_src = (float*)&As[0][0];
        float* sm_dst = sm_src + 2 * GBM;
        __syncthreads();
        if (tg == 0) {
#pragma unroll
            for (int mt = 0; mt < 2; mt++)
#pragma unroll
                for (int rr = 0; rr < 2; rr++) {
                    int rl = wm * 32 + mt * 16 + g + rr * 8;
                    sm_src[wn * GBM + rl] = ps[mt][rr];
                    sm_dst[wn * GBM + rl] = pd[mt][rr];
                }
        }
        __syncthreads();
        if (tid < GBM) {
            int r = row0 + tid;
            if (r < M) {
                g_esrc[(size_t)r * H + head] = sm_src[tid] + sm_src[GBM + tid];
                g_edst[(size_t)r * H + head] = sm_dst[tid] + sm_dst[GBM + tid];
            }
        }
    }
}

// ---------------- fused gather softmax + aggregation (x2 unroll) ----------------
template <int H, bool RELU, bool OUT16, bool POOL>
__global__ void gat_agg_kernel(const int* __restrict__ rowptr,
                               const int* __restrict__ srclist,
                               const float* __restrict__ esrc,
                               const float* __restrict__ edst,
                               const uint4* __restrict__ hv4,
                               const float* __restrict__ bias,
                               __half* __restrict__ outh,
                               const int* __restrict__ batch) {
    constexpr int HC  = H * 64;
    constexpr int TPG = HC / 8;
    constexpr int NPB = 128 / TPG;
    int node = blockIdx.x * NPB + threadIdx.x / TPG;
    bool active = (node < N_NODES);
    int t = threadIdx.x % TPG;
    int head = (H == 1) ? 0 : (t >> 3);

    __shared__ float sp[POOL ? 4 * 64 : 1];
    __shared__ float scnt[POOL ? 4 : 1];
    __shared__ int   sg0[1];
    int gbase = 0, grel = 0;
    if (POOL) {
        if (threadIdx.x == 0) sg0[0] = batch[min(blockIdx.x * NPB, N_NODES - 1)];
        for (int i = threadIdx.x; i < 4 * 64; i += 128) sp[i] = 0.f;
        if (threadIdx.x < 4) scnt[threadIdx.x] = 0.f;
        __syncthreads();
        gbase = sg0[0];
        if (active) grel = min(batch[node] - gbase, 3);
    }

    float acc[8] = {};
    float denom = 0.f;

    if (active) {
        int beg = rowptr[node];
        int end = rowptr[node + 1];
        float ed = edst[node * H + head];
        int i = beg;
        for (; i + 2 <= end; i += 2) {
            int s0 = srclist[i];
            int s1 = srclist[i + 1];
            float es0 = esrc[s0 * H + head];
            float es1 = esrc[s1 * H + head];
            uint4 u0 = hv4[(size_t)s0 * TPG + t];
            uint4 u1 = hv4[(size_t)s1 * TPG + t];
            float e0 = es0 + ed; e0 = (e0 > 0.f) ? e0 : NEG_SLOPE * e0;
            float e1 = es1 + ed; e1 = (e1 > 0.f) ? e1 : NEG_SLOPE * e1;
            float x0 = __expf(e0);
            float x1 = __expf(e1);
            denom += x0;
            denom += x1;
            unsigned uu0[4] = {u0.x, u0.y, u0.z, u0.w};
            unsigned uu1[4] = {u1.x, u1.y, u1.z, u1.w};
#pragma unroll
            for (int k = 0; k < 4; k++) {
                float2 f0 = __half22float2(*reinterpret_cast<__half2*>(&uu0[k]));
                float2 f1 = __half22float2(*reinterpret_cast<__half2*>(&uu1[k]));
                acc[2 * k]     = fmaf(x0, f0.x, acc[2 * k]);
                acc[2 * k + 1] = fmaf(x0, f0.y, acc[2 * k + 1]);
                acc[2 * k]     = fmaf(x1, f1.x, acc[2 * k]);
                acc[2 * k + 1] = fmaf(x1, f1.y, acc[2 * k + 1]);
            }
        }
        if (i < end) {
            int s = srclist[i];
            float e = esrc[s * H + head] + ed;
            e = (e > 0.f) ? e : NEG_SLOPE * e;
            float ex = __expf(e);
            denom += ex;
            uint4 u = hv4[(size_t)s * TPG + t];
            unsigned uu[4] = {u.x, u.y, u.z, u.w};
#pragma unroll
            for (int k = 0; k < 4; k++) {
                float2 f = __half22float2(*reinterpret_cast<__half2*>(&uu[k]));
                acc[2 * k]     = fmaf(ex, f.x, acc[2 * k]);
                acc[2 * k + 1] = fmaf(ex, f.y, acc[2 * k + 1]);
            }
        }
    }

    float inv = active ? 1.f / (denom + 1e-16f) : 0.f;
    int c0 = t * 8;
    float o[8];
#pragma unroll
    for (int k = 0; k < 8; k++) {
        float v = acc[k] * inv + (active ? bias[c0 + k] : 0.f);
        o[k] = RELU ? fmaxf(v, 0.f) : v;
    }
    if (OUT16) {
        if (active) {
            __half hbuf[8];
#pragma unroll
            for (int k = 0; k < 8; k++) hbuf[k] = __float2half(o[k]);
            *(uint4*)&outh[(size_t)node * HC + c0] = *(uint4*)hbuf;
        }
    }
    if (POOL) {
        if (active) {
#pragma unroll
            for (int k = 0; k < 8; k++)
                atomicAdd(&sp[grel * 64 + c0 + k], o[k]);
            if (t == 0) atomicAdd(&scnt[grel], 1.f);
        }
        __syncthreads();
        for (int i = threadIdx.x; i < 4 * 64; i += 128) {
            float v = sp[i];
            if (v != 0.f) atomicAdd(&g_pool[(gbase + (i >> 6)) * 64 + (i & 63)], v);
        }
        if (threadIdx.x < 4 && scnt[threadIdx.x] != 0.f)
            atomicAdd(&g_cnt[gbase + threadIdx.x], scnt[threadIdx.x]);
    }
}

__global__ void finalize_kernel(const float* __restrict__ lin_w,
                                const float* __restrict__ lin_b,
                                float* __restrict__ out) {
    int g = threadIdx.x;
    float cnt = fmaxf(g_cnt[g], 1.f);
    float s = 0.f;
    for (int c = 0; c < 64; c++)
        s += g_pool[g * 64 + c] * lin_w[c];
    out[g] = s / cnt + lin_b[0];
}

// ---------------- launch ----------------
extern "C" void kernel_launch(void* const* d_in, const int* in_sizes, int n_in,
                              void* d_out, int out_size) {
    (void)in_sizes; (void)n_in; (void)out_size;
    const float* x      = (const float*)d_in[0];
    const int*   ei     = (const int*)  d_in[1];
    const int*   batch  = (const int*)  d_in[2];
    const float* W0     = (const float*)d_in[3];
    const float* asrc0  = (const float*)d_in[4];
    const float* adst0  = (const float*)d_in[5];
    const float* b0     = (const float*)d_in[6];
    const float* W1     = (const float*)d_in[7];
    const float* asrc1  = (const float*)d_in[8];
    const float* adst1  = (const float*)d_in[9];
    const float* b1     = (const float*)d_in[10];
    const float* W2     = (const float*)d_in[11];
    const float* asrc2  = (const float*)d_in[12];
    const float* adst2  = (const float*)d_in[13];
    const float* b2     = (const float*)d_in[14];
    const float* lin_w  = (const float*)d_in[15];
    const float* lin_b  = (const float*)d_in[16];
    float* out = (float*)d_out;

    static cudaStream_t s2 = nullptr;
    static cudaEvent_t ev1 = nullptr, ev2 = nullptr;
    if (!s2) {
        cudaStreamCreateWithFlags(&s2, cudaStreamNonBlocking);
        cudaEventCreateWithFlags(&ev1, cudaEventDisableTiming);
        cudaEventCreateWithFlags(&ev2, cudaEventDisableTiming);
    }

    void *p_acth_v, *p_pool_v, *p_cnt_v;
    void *p_row_v, *p_src_v, *p_es_v, *p_ed_v, *p_hth_v;
    cudaGetSymbolAddress(&p_acth_v, g_acth);
    cudaGetSymbolAddress(&p_pool_v, g_pool);
    cudaGetSymbolAddress(&p_cnt_v, g_cnt);
    cudaGetSymbolAddress(&p_row_v, g_rowptr);
    cudaGetSymbolAddress(&p_src_v, g_srclist);
    cudaGetSymbolAddress(&p_es_v, g_esrc);
    cudaGetSymbolAddress(&p_ed_v, g_edst);
    cudaGetSymbolAddress(&p_hth_v, g_hth);
    __half* p_acth = (__half*)p_acth_v;
    const int* p_row = (const int*)p_row_v;
    const int* p_src = (const int*)p_src_v;
    const float* p_es = (const float*)p_es_v;
    const float* p_ed = (const float*)p_ed_v;
    const uint4* p_hv = (const uint4*)p_hth_v;

    dim3 grid_big(2, (N_NODES + GBM - 1) / GBM);    // GBNP=128
    dim3 grid_sml(1, (N_NODES + GBM - 1) / GBM);    // GBNP=64

    // ---- single fork: CSR build + memsets on side stream ----
    cudaEventRecord(ev1, 0);
    cudaStreamWaitEvent(s2, ev1, 0);
    cudaMemsetAsync(p_pool_v, 0, NGRAPH * 64 * sizeof(float), s2);
    cudaMemsetAsync(p_cnt_v, 0, NGRAPH * sizeof(float), s2);
    deg_init_kernel<<<(N_NODES + 255) / 256, 256, 0, s2>>>();
    count_deg_edges_kernel<<<(ECH + 255) / 256, 256, 0, s2>>>(ei);
    scan_rowptr_fused_kernel<<<NBLK_SCAN, 256, 0, s2>>>();
    fill_csr_kernel<<<(ECH + 255) / 256, 256, 0, s2>>>(ei);
    cudaEventRecord(ev2, s2);

    // ---- main stream: GEMM0 overlaps CSR build; single join before agg0 ----
    hgemm_attn_kernel<128, true><<<grid_big, 256>>>(x, W0, asrc0, adst0, N_NODES, 128, 256, 4);
    cudaStreamWaitEvent(0, ev2, 0);
    gat_agg_kernel<4, true, true, false><<<(N_NODES + 3) / 4, 128>>>(
        p_row, p_src, p_es, p_ed, p_hv, b0, p_acth, nullptr);

    hgemm_attn_kernel<128, false><<<grid_big, 256>>>(p_acth, W1, asrc1, adst1, N_NODES, 256, 256, 4);
    gat_agg_kernel<4, true, true, false><<<(N_NODES + 3) / 4, 128>>>(
        p_row, p_src, p_es, p_ed, p_hv, b1, p_acth, nullptr);

    hgemm_attn_kernel<64, false><<<grid_sml, 256>>>(p_acth, W2, asrc2, adst2, N_NODES, 256, 64, 1);
    gat_agg_kernel<1, false, false, true><<<(N_NODES + 15) / 16, 128>>>(
        p_row, p_src, p_es, p_ed, p_hv, b2, nullptr, batch);

    finalize_kernel<<<1, 64>>>(lin_w, lin_b, out);
}

// round 15
// speedup vs baseline: 1.0340x; 1.0093x over previous
#include <cuda_runtime.h>
#include <cuda_fp16.h>
#include <math.h>

// ---------------- problem constants ----------------
#define N_NODES 50000
#define E_EDGES 800000
#define ET (E_EDGES + N_NODES)
#define NGRAPH 64
#define NEG_SLOPE 0.2f
#define NBLK_SCAN 196            // ceil(50000/256)
#define ECH8 (E_EDGES / 8)       // 100000 8-edge chunks

// ---------------- device scratch ----------------
__device__ __half g_hth [N_NODES * 256];
__device__ __half g_acth[N_NODES * 256];
__device__ float  g_esrc[N_NODES * 4];
__device__ float  g_edst[N_NODES * 4];
__device__ int    g_deg   [N_NODES];
__device__ int    g_rowptr[N_NODES + 1];
__device__ int    g_cursor[N_NODES];
__device__ int    g_srclist[ET];
__device__ int    g_bsum[256];
__device__ int    g_boff[256];
__device__ float  g_pool[NGRAPH * 64];
__device__ float  g_cnt [NGRAPH];
__device__ int    g_arrive = 0;
__device__ int    g_flag   = 0;
__device__ int    g_donect = 0;

// ---------------- CSR build (by destination) ----------------
// deg starts at 0 (memset); self-loop +1 folded into the scan below.
__global__ void count_deg_edges_kernel(const int* __restrict__ ei) {
    int i = blockIdx.x * blockDim.x + threadIdx.x;   // 8 edges per thread
    if (i >= ECH8) return;
    const int4* dp = reinterpret_cast<const int4*>(ei + E_EDGES);
    int4 d0 = dp[2 * i];
    int4 d1 = dp[2 * i + 1];
    atomicAdd(&g_deg[d0.x], 1);
    atomicAdd(&g_deg[d0.y], 1);
    atomicAdd(&g_deg[d0.z], 1);
    atomicAdd(&g_deg[d0.w], 1);
    atomicAdd(&g_deg[d1.x], 1);
    atomicAdd(&g_deg[d1.y], 1);
    atomicAdd(&g_deg[d1.z], 1);
    atomicAdd(&g_deg[d1.w], 1);
}

// Fused 3-phase scan: block scan -> cross-block scan -> rowptr fill.
// Includes self-loop +1. Grid-wide sync via spin barrier (196 blocks < 148 SMs x occ).
__global__ void scan_rowptr_fused_kernel() {
    int t = threadIdx.x, b = blockIdx.x;
    int idx = b * 256 + t;
    int lane = t & 31, w = t >> 5;

    // --- phase 1: block-local inclusive scan + block sum ---
    int v = (idx < N_NODES) ? (g_deg[idx] + 1) : 0;   // +1 = self loop
    int sc = v;
#pragma unroll
    for (int o = 1; o < 32; o <<= 1) {
        int u = __shfl_up_sync(0xFFFFFFFFu, sc, o);
        if (lane >= o) sc += u;
    }
    __shared__ int ws[8];
    if (lane == 31) ws[w] = sc;
    __syncthreads();
    if (t < 8) {
        int x = ws[t];
#pragma unroll
        for (int o = 1; o < 8; o <<= 1) {
            int u = __shfl_up_sync(0xFFu, x, o);
            if (t >= o) x += u;
        }
        ws[t] = x;
    }
    __syncthreads();
    int blocksum = ws[7];
    if (t == 0) {
        g_bsum[b] = blocksum;
        __threadfence();
        atomicAdd(&g_arrive, 1);
    }

    // --- phase 2: block 0 scans the 196 block sums ---
    if (b == 0) {
        if (t == 0) {
            while (atomicAdd(&g_arrive, 0) < NBLK_SCAN) __nanosleep(64);
        }
        __syncthreads();
        int v2 = (t < NBLK_SCAN) ? g_bsum[t] : 0;
        int sc2 = v2;
#pragma unroll
        for (int o = 1; o < 32; o <<= 1) {
            int u = __shfl_up_sync(0xFFFFFFFFu, sc2, o);
            if (lane >= o) sc2 += u;
        }
        __shared__ int ws2[8];
        if (lane == 31) ws2[w] = sc2;
        __syncthreads();
        if (t < 8) {
            int x = ws2[t];
#pragma unroll
            for (int o = 1; o < 8; o <<= 1) {
                int u = __shfl_up_sync(0xFFu, x, o);
                if (t >= o) x += u;
            }
            ws2[t] = x;
        }
        __syncthreads();
        int incl = sc2 + (w > 0 ? ws2[w - 1] : 0);
        g_boff[t] = incl - v2;
        if (t == NBLK_SCAN - 1) g_rowptr[N_NODES] = incl;
        __threadfence();
        __syncthreads();
        if (t == 0) atomicExch(&g_flag, 1);
    }

    // --- phase 3: all blocks wait, then fill rowptr/cursor/self-loop ---
    if (t == 0) {
        while (atomicAdd(&g_flag, 0) == 0) __nanosleep(64);
    }
    __syncthreads();
    if (idx < N_NODES) {
        int excl = g_boff[b] + (w > 0 ? ws[w - 1] : 0) + sc - v;
        g_rowptr[idx] = excl;
        g_cursor[idx] = excl + 1;         // slot 0 reserved for self loop
        g_srclist[excl] = idx;            // self loop filled here
    }
    // --- reset sync state for graph replay determinism ---
    __syncthreads();
    if (t == 0) {
        int d = atomicAdd(&g_donect, 1);
        if (d == NBLK_SCAN - 1) {
            g_arrive = 0;
            g_flag   = 0;
            g_donect = 0;
            __threadfence();
        }
    }
}

__global__ void fill_csr_kernel(const int* __restrict__ ei) {
    int i = blockIdx.x * blockDim.x + threadIdx.x;   // 8 edges per thread
    if (i >= ECH8) return;
    const int4* sp = reinterpret_cast<const int4*>(ei);
    const int4* dp = reinterpret_cast<const int4*>(ei + E_EDGES);
    int4 s0 = sp[2 * i],     s1 = sp[2 * i + 1];
    int4 d0 = dp[2 * i],     d1 = dp[2 * i + 1];
    int p0 = atomicAdd(&g_cursor[d0.x], 1);
    int p1 = atomicAdd(&g_cursor[d0.y], 1);
    int p2 = atomicAdd(&g_cursor[d0.z], 1);
    int p3 = atomicAdd(&g_cursor[d0.w], 1);
    int p4 = atomicAdd(&g_cursor[d1.x], 1);
    int p5 = atomicAdd(&g_cursor[d1.y], 1);
    int p6 = atomicAdd(&g_cursor[d1.z], 1);
    int p7 = atomicAdd(&g_cursor[d1.w], 1);
    g_srclist[p0] = s0.x;
    g_srclist[p1] = s0.y;
    g_srclist[p2] = s0.z;
    g_srclist[p3] = s0.w;
    g_srclist[p4] = s1.x;
    g_srclist[p5] = s1.y;
    g_srclist[p6] = s1.z;
    g_srclist[p7] = s1.w;
}

// ---------------- fp16 tensor-core GEMM + fused attention epilogue ----------------
__device__ __forceinline__ void mma_f16(float* c, const unsigned* a, const unsigned* b) {
    asm volatile(
        "mma.sync.aligned.m16n8k16.row.col.f32.f16.f16.f32 "
        "{%0,%1,%2,%3},{%4,%5,%6,%7},{%8,%9},{%0,%1,%2,%3};"
        : "+f"(c[0]), "+f"(c[1]), "+f"(c[2]), "+f"(c[3])
        : "r"(a[0]), "r"(a[1]), "r"(a[2]), "r"(a[3]), "r"(b[0]), "r"(b[1]));
}

__device__ __forceinline__ void ldsm_x4(unsigned& r0, unsigned& r1, unsigned& r2,
                                        unsigned& r3, unsigned addr) {
    asm volatile("ldmatrix.sync.aligned.m8n8.x4.shared.b16 {%0,%1,%2,%3}, [%4];"
                 : "=r"(r0), "=r"(r1), "=r"(r2), "=r"(r3) : "r"(addr));
}

#define GBM 128
#define GBK 32
#define A_STRH 40
#define B_STRH 40

template <int GBNP, bool A32>
__global__ __launch_bounds__(256, 2)
void hgemm_attn_kernel(const void* __restrict__ Araw, const float* __restrict__ B,
                       const float* __restrict__ asrc, const float* __restrict__ adst,
                       int M, int K, int Nd, int H) {
    constexpr int NT   = GBNP / 16;
    constexpr int NGRP = 256 / GBNP;
    constexpr int KPG  = GBK / NGRP;
    __shared__ __half As[2][GBM * A_STRH];
    __shared__ __half Bs[2][GBNP * B_STRH];

    const int tid  = threadIdx.x;
    const int warp = tid >> 5, lane = tid & 31;
    const int wm = warp >> 1, wn = warp & 1;
    const int row0 = blockIdx.y * GBM, col0 = blockIdx.x * GBNP;
    const int g = lane >> 2, tg = lane & 3;
    const int ar = tid >> 1, ahf = (tid & 1) * 16;
    const int bn = tid % GBNP, bkq = (tid / GBNP) * KPG;

    const unsigned As_sh = (unsigned)__cvta_generic_to_shared(&As[0][0]);
    const unsigned Bs_sh = (unsigned)__cvta_generic_to_shared(&Bs[0][0]);
    const int a_lsel = (lane & 15) * A_STRH + (lane >> 4) * 8;
    const int b_lsel = (((lane >> 4) & 1) * 8 + (lane & 7)) * B_STRH + ((lane >> 3) & 1) * 8;

    float acc[2][NT][4] = {};
    uint4 a_pre[2];
    float afp[A32 ? 16 : 1];
    __half b_pre[KPG];

    auto ldg = [&](int k0) {
        bool ok = (row0 + ar) < M;
        if (A32) {
            const float* ap = (const float*)Araw + (size_t)(row0 + ar) * K + k0 + ahf;
#pragma unroll
            for (int j = 0; j < 4; j++)
                *(float4*)&afp[4 * j] = ok ? *(const float4*)(ap + 4 * j)
                                           : make_float4(0.f, 0.f, 0.f, 0.f);
        } else {
            const __half* ap = (const __half*)Araw + (size_t)(row0 + ar) * K + k0 + ahf;
            a_pre[0] = ok ? *(const uint4*)ap       : make_uint4(0, 0, 0, 0);
            a_pre[1] = ok ? *(const uint4*)(ap + 8) : make_uint4(0, 0, 0, 0);
        }
#pragma unroll
        for (int i = 0; i < KPG; i++)
            b_pre[i] = __float2half(B[(size_t)(k0 + bkq + i) * Nd + col0 + bn]);
    };
    auto sts = [&](int s) {
        if (A32) {
            __half ha[16];
#pragma unroll
            for (int j = 0; j < 16; j++) ha[j] = __float2half(afp[j]);
            *(uint4*)&As[s][ar * A_STRH + ahf]     = ((uint4*)ha)[0];
            *(uint4*)&As[s][ar * A_STRH + ahf + 8] = ((uint4*)ha)[1];
        } else {
            *(uint4*)&As[s][ar * A_STRH + ahf]     = a_pre[0];
            *(uint4*)&As[s][ar * A_STRH + ahf + 8] = a_pre[1];
        }
#pragma unroll
        for (int j = 0; j < KPG / 8; j++)
            *(uint4*)&Bs[s][bn * B_STRH + bkq + 8 * j] = *(uint4*)&b_pre[8 * j];
    };
    auto compute = [&](int s) {
#pragma unroll
        for (int ks = 0; ks < 2; ks++) {
            unsigned afr[2][4];
#pragma unroll
            for (int mt = 0; mt < 2; mt++) {
                unsigned addr = As_sh +
                    (unsigned)((s * GBM * A_STRH) +
                               (wm * 32 + mt * 16) * A_STRH + ks * 16 + a_lsel) * 2u;
                ldsm_x4(afr[mt][0], afr[mt][1], afr[mt][2], afr[mt][3], addr);
            }
            unsigned bfr[NT][2];
#pragma unroll
            for (int p = 0; p < NT / 2; p++) {
                unsigned addr = Bs_sh +
                    (unsigned)((s * GBNP * B_STRH) +
                               (wn * (GBNP / 2) + p * 16) * B_STRH + ks * 16 + b_lsel) * 2u;
                ldsm_x4(bfr[2 * p][0], bfr[2 * p][1], bfr[2 * p + 1][0], bfr[2 * p + 1][1], addr);
            }
#pragma unroll
            for (int mt = 0; mt < 2; mt++)
#pragma unroll
                for (int nt = 0; nt < NT; nt++)
                    mma_f16(acc[mt][nt], afr[mt], bfr[nt]);
        }
    };

    ldg(0); sts(0); __syncthreads();
    int nk = K / GBK;
    for (int i = 0; i < nk; i++) {
        if (i + 1 < nk) ldg((i + 1) * GBK);
        compute(i & 1);
        if (i + 1 < nk) sts((i + 1) & 1);
        __syncthreads();
    }

    // ---- epilogue 1: fp16 feature store ----
#pragma unroll
    for (int mt = 0; mt < 2; mt++)
#pragma unroll
        for (int nt = 0; nt < NT; nt++) {
            int r = row0 + wm * 32 + mt * 16 + g;
            int c = col0 + wn * (GBNP / 2) + nt * 8 + 2 * tg;
            if (r < M)
                *(__half2*)&g_hth[(size_t)r * Nd + c] =
                    __floats2half2_rn(acc[mt][nt][0], acc[mt][nt][1]);
            if (r + 8 < M)
                *(__half2*)&g_hth[(size_t)(r + 8) * Nd + c] =
                    __floats2half2_rn(acc[mt][nt][2], acc[mt][nt][3]);
        }

    // ---- epilogue 2: attention coefficients ----
    float ps[2][2] = {}, pd[2][2] = {};
    const int head = (GBNP == 64) ? blockIdx.x : (blockIdx.x * 2 + wn);
    const int hb = head * 64;
#pragma unroll
    for (int nt = 0; nt < NT; nt++) {
        int cl = (GBNP == 64) ? (wn * 32 + nt * 8 + 2 * tg) : (nt * 8 + 2 * tg);
        float as0 = asrc[hb + cl], as1 = asrc[hb + cl + 1];
        float ad0 = adst[hb + cl], ad1 = adst[hb + cl + 1];
#pragma unroll
        for (int mt = 0; mt < 2; mt++) {
            ps[mt][0] += acc[mt][nt][0] * as0 + acc[mt][nt][1] * as1;
            ps[mt][1] += acc[mt][nt][2] * as0 + acc[mt][nt][3] * as1;
            pd[mt][0] += acc[mt][nt][0] * ad0 + acc[mt][nt][1] * ad1;
            pd[mt][1] += acc[mt][nt][2] * ad0 + acc[mt][nt][3] * ad1;
        }
    }
#pragma unroll
    for (int o = 1; o < 4; o <<= 1) {
#pragma unroll
        for (int mt = 0; mt < 2; mt++)
#pragma unroll
            for (int rr = 0; rr < 2; rr++) {
                ps[mt][rr] += __shfl_xor_sync(0xFFFFFFFFu, ps[mt][rr], o);
                pd[mt][rr] += __shfl_xor_sync(0xFFFFFFFFu, pd[mt][rr], o);
            }
    }
    if (GBNP == 128) {
        if (tg == 0) {
#pragma unroll
            for (int mt = 0; mt < 2; mt++)
#pragma unroll
                for (int rr = 0; rr < 2; rr++) {
                    int r = row0 + wm * 32 + mt * 16 + g + rr * 8;
                    if (r < M) {
                        g_esrc[(size_t)r * H + head] = ps[mt][rr];
                        g_edst[(size_t)r * H + head] = pd[mt][rr];
                    }
                }
        }
    } else {
        float* sm_src = (float*)&As[0][0];
        float* sm_dst = sm_src + 2 * GBM;
        __syncthreads();
        if (tg == 0) {
#pragma unroll
            for (int mt = 0; mt < 2; mt++)
#pragma unroll
                for (int rr = 0; rr < 2; rr++) {
                    int rl = wm * 32 + mt * 16 + g + rr * 8;
                    sm_src[wn * GBM + rl] = ps[mt][rr];
                    sm_dst[wn * GBM + rl] = pd[mt][rr];
                }
        }
        __syncthreads();
        if (tid < GBM) {
            int r = row0 + tid;
            if (r < M) {
                g_esrc[(size_t)r * H + head] = sm_src[tid] + sm_src[GBM + tid];
                g_edst[(size_t)r * H + head] = sm_dst[tid] + sm_dst[GBM + tid];
            }
        }
    }
}

// ---------------- fused gather softmax + aggregation (x2 unroll) ----------------
template <int H, bool RELU, bool OUT16, bool POOL>
__global__ void gat_agg_kernel(const int* __restrict__ rowptr,
                               const int* __restrict__ srclist,
                               const float* __restrict__ esrc,
                               const float* __restrict__ edst,
                               const uint4* __restrict__ hv4,
                               const float* __restrict__ bias,
                               __half* __restrict__ outh,
                               const int* __restrict__ batch) {
    constexpr int HC  = H * 64;
    constexpr int TPG = HC / 8;
    constexpr int NPB = 128 / TPG;
    int node = blockIdx.x * NPB + threadIdx.x / TPG;
    bool active = (node < N_NODES);
    int t = threadIdx.x % TPG;
    int head = (H == 1) ? 0 : (t >> 3);

    __shared__ float sp[POOL ? 4 * 64 : 1];
    __shared__ float scnt[POOL ? 4 : 1];
    __shared__ int   sg0[1];
    int gbase = 0, grel = 0;
    if (POOL) {
        if (threadIdx.x == 0) sg0[0] = batch[min(blockIdx.x * NPB, N_NODES - 1)];
        for (int i = threadIdx.x; i < 4 * 64; i += 128) sp[i] = 0.f;
        if (threadIdx.x < 4) scnt[threadIdx.x] = 0.f;
        __syncthreads();
        gbase = sg0[0];
        if (active) grel = min(batch[node] - gbase, 3);
    }

    float acc[8] = {};
    float denom = 0.f;

    if (active) {
        int beg = rowptr[node];
        int end = rowptr[node + 1];
        float ed = edst[node * H + head];
        int i = beg;
        for (; i + 2 <= end; i += 2) {
            int s0 = srclist[i];
            int s1 = srclist[i + 1];
            float es0 = esrc[s0 * H + head];
            float es1 = esrc[s1 * H + head];
            uint4 u0 = hv4[(size_t)s0 * TPG + t];
            uint4 u1 = hv4[(size_t)s1 * TPG + t];
            float e0 = es0 + ed; e0 = (e0 > 0.f) ? e0 : NEG_SLOPE * e0;
            float e1 = es1 + ed; e1 = (e1 > 0.f) ? e1 : NEG_SLOPE * e1;
            float x0 = __expf(e0);
            float x1 = __expf(e1);
            denom += x0;
            denom += x1;
            unsigned uu0[4] = {u0.x, u0.y, u0.z, u0.w};
            unsigned uu1[4] = {u1.x, u1.y, u1.z, u1.w};
#pragma unroll
            for (int k = 0; k < 4; k++) {
                float2 f0 = __half22float2(*reinterpret_cast<__half2*>(&uu0[k]));
                float2 f1 = __half22float2(*reinterpret_cast<__half2*>(&uu1[k]));
                acc[2 * k]     = fmaf(x0, f0.x, acc[2 * k]);
                acc[2 * k + 1] = fmaf(x0, f0.y, acc[2 * k + 1]);
                acc[2 * k]     = fmaf(x1, f1.x, acc[2 * k]);
                acc[2 * k + 1] = fmaf(x1, f1.y, acc[2 * k + 1]);
            }
        }
        if (i < end) {
            int s = srclist[i];
            float e = esrc[s * H + head] + ed;
            e = (e > 0.f) ? e : NEG_SLOPE * e;
            float ex = __expf(e);
            denom += ex;
            uint4 u = hv4[(size_t)s * TPG + t];
            unsigned uu[4] = {u.x, u.y, u.z, u.w};
#pragma unroll
            for (int k = 0; k < 4; k++) {
                float2 f = __half22float2(*reinterpret_cast<__half2*>(&uu[k]));
                acc[2 * k]     = fmaf(ex, f.x, acc[2 * k]);
                acc[2 * k + 1] = fmaf(ex, f.y, acc[2 * k + 1]);
            }
        }
    }

    float inv = active ? 1.f / (denom + 1e-16f) : 0.f;
    int c0 = t * 8;
    float o[8];
#pragma unroll
    for (int k = 0; k < 8; k++) {
        float v = acc[k] * inv + (active ? bias[c0 + k] : 0.f);
        o[k] = RELU ? fmaxf(v, 0.f) : v;
    }
    if (OUT16) {
        if (active) {
            __half hbuf[8];
#pragma unroll
            for (int k = 0; k < 8; k++) hbuf[k] = __float2half(o[k]);
            *(uint4*)&outh[(size_t)node * HC + c0] = *(uint4*)hbuf;
        }
    }
    if (POOL) {
        if (active) {
#pragma unroll
            for (int k = 0; k < 8; k++)
                atomicAdd(&sp[grel * 64 + c0 + k], o[k]);
            if (t == 0) atomicAdd(&scnt[grel], 1.f);
        }
        __syncthreads();
        for (int i = threadIdx.x; i < 4 * 64; i += 128) {
            float v = sp[i];
            if (v != 0.f) atomicAdd(&g_pool[(gbase + (i >> 6)) * 64 + (i & 63)], v);
        }
        if (threadIdx.x < 4 && scnt[threadIdx.x] != 0.f)
            atomicAdd(&g_cnt[gbase + threadIdx.x], scnt[threadIdx.x]);
    }
}

__global__ void finalize_kernel(const float* __restrict__ lin_w,
                                const float* __restrict__ lin_b,
                                float* __restrict__ out) {
    int g = threadIdx.x;
    float cnt = fmaxf(g_cnt[g], 1.f);
    float s = 0.f;
    for (int c = 0; c < 64; c++)
        s += g_pool[g * 64 + c] * lin_w[c];
    out[g] = s / cnt + lin_b[0];
}

// ---------------- launch ----------------
extern "C" void kernel_launch(void* const* d_in, const int* in_sizes, int n_in,
                              void* d_out, int out_size) {
    (void)in_sizes; (void)n_in; (void)out_size;
    const float* x      = (const float*)d_in[0];
    const int*   ei     = (const int*)  d_in[1];
    const int*   batch  = (const int*)  d_in[2];
    const float* W0     = (const float*)d_in[3];
    const float* asrc0  = (const float*)d_in[4];
    const float* adst0  = (const float*)d_in[5];
    const float* b0     = (const float*)d_in[6];
    const float* W1     = (const float*)d_in[7];
    const float* asrc1  = (const float*)d_in[8];
    const float* adst1  = (const float*)d_in[9];
    const float* b1     = (const float*)d_in[10];
    const float* W2     = (const float*)d_in[11];
    const float* asrc2  = (const float*)d_in[12];
    const float* adst2  = (const float*)d_in[13];
    const float* b2     = (const float*)d_in[14];
    const float* lin_w  = (const float*)d_in[15];
    const float* lin_b  = (const float*)d_in[16];
    float* out = (float*)d_out;

    static cudaStream_t s2 = nullptr;
    static cudaEvent_t ev1 = nullptr, ev2 = nullptr;
    if (!s2) {
        cudaStreamCreateWithFlags(&s2, cudaStreamNonBlocking);
        cudaEventCreateWithFlags(&ev1, cudaEventDisableTiming);
        cudaEventCreateWithFlags(&ev2, cudaEventDisableTiming);
    }

    void *p_acth_v, *p_pool_v, *p_cnt_v, *p_deg_v;
    void *p_row_v, *p_src_v, *p_es_v, *p_ed_v, *p_hth_v;
    cudaGetSymbolAddress(&p_acth_v, g_acth);
    cudaGetSymbolAddress(&p_pool_v, g_pool);
    cudaGetSymbolAddress(&p_cnt_v, g_cnt);
    cudaGetSymbolAddress(&p_deg_v, g_deg);
    cudaGetSymbolAddress(&p_row_v, g_rowptr);
    cudaGetSymbolAddress(&p_src_v, g_srclist);
    cudaGetSymbolAddress(&p_es_v, g_esrc);
    cudaGetSymbolAddress(&p_ed_v, g_edst);
    cudaGetSymbolAddress(&p_hth_v, g_hth);
    __half* p_acth = (__half*)p_acth_v;
    const int* p_row = (const int*)p_row_v;
    const int* p_src = (const int*)p_src_v;
    const float* p_es = (const float*)p_es_v;
    const float* p_ed = (const float*)p_ed_v;
    const uint4* p_hv = (const uint4*)p_hth_v;

    dim3 grid_big(2, (N_NODES + GBM - 1) / GBM);    // GBNP=128
    dim3 grid_sml(1, (N_NODES + GBM - 1) / GBM);    // GBNP=64

    // ---- single fork: CSR build on side stream ----
    cudaEventRecord(ev1, 0);
    cudaStreamWaitEvent(s2, ev1, 0);
    cudaMemsetAsync(p_deg_v, 0, N_NODES * sizeof(int), s2);
    count_deg_edges_kernel<<<(ECH8 + 255) / 256, 256, 0, s2>>>(ei);
    scan_rowptr_fused_kernel<<<NBLK_SCAN, 256, 0, s2>>>();
    fill_csr_kernel<<<(ECH8 + 255) / 256, 256, 0, s2>>>(ei);
    cudaEventRecord(ev2, s2);

    // ---- main stream ----
    cudaMemsetAsync(p_pool_v, 0, NGRAPH * 64 * sizeof(float));
    cudaMemsetAsync(p_cnt_v, 0, NGRAPH * sizeof(float));
    hgemm_attn_kernel<128, true><<<grid_big, 256>>>(x, W0, asrc0, adst0, N_NODES, 128, 256, 4);
    cudaStreamWaitEvent(0, ev2, 0);
    gat_agg_kernel<4, true, true, false><<<(N_NODES + 3) / 4, 128>>>(
        p_row, p_src, p_es, p_ed, p_hv, b0, p_acth, nullptr);

    hgemm_attn_kernel<128, false><<<grid_big, 256>>>(p_acth, W1, asrc1, adst1, N_NODES, 256, 256, 4);
    gat_agg_kernel<4, true, true, false><<<(N_NODES + 3) / 4, 128>>>(
        p_row, p_src, p_es, p_ed, p_hv, b1, p_acth, nullptr);

    hgemm_attn_kernel<64, false><<<grid_sml, 256>>>(p_acth, W2, asrc2, adst2, N_NODES, 256, 64, 1);
    gat_agg_kernel<1, false, false, true><<<(N_NODES + 15) / 16, 128>>>(
        p_row, p_src, p_es, p_ed, p_hv, b2, nullptr, batch);

    finalize_kernel<<<1, 64>>>(lin_w, lin_b, out);
}